// round 1
// baseline (speedup 1.0000x reference)
#include <cuda_runtime.h>
#include <cstdint>
#include <math.h>

// ---------------------------------------------------------------------------
// Problem dims
// ---------------------------------------------------------------------------
constexpr int B_   = 256;
constexpr int R_   = 6;
constexpr int K_   = 49;
constexpr int C_   = 512;
constexpr int H_   = 1024;
constexpr int E_   = 300;
constexpr int BR_  = B_ * R_;          // 1536
constexpr int NL_  = 2001;
constexpr int TWO_E = 2 * E_;          // 600
constexpr int CATW  = H_ + TWO_E;      // 1624

// ---------------------------------------------------------------------------
// Scratch layout (single __device__ buffer, constexpr offsets)
// ---------------------------------------------------------------------------
constexpr long SZ_IMG0 = (long)B_ * K_ * C_;    // 6,422,528
constexpr long SZ_V    = (long)B_ * K_ * H_;    // 12,845,056
constexpr long SZ_RV   = (long)BR_ * TWO_E;
constexpr long SZ_H    = (long)BR_ * H_;
constexpr long SZ_C    = (long)BR_ * C_;
constexpr long SZ_CAT  = (long)BR_ * CATW;

constexpr long OFF_IMG0  = 0;
constexpr long OFF_V1    = OFF_IMG0  + SZ_IMG0;
constexpr long OFF_V2    = OFF_V1    + SZ_V;
constexpr long OFF_RV    = OFF_V2    + SZ_V;
constexpr long OFF_QEMB  = OFF_RV    + SZ_RV;
constexpr long OFF_QA    = OFF_QEMB  + SZ_H;
constexpr long OFF_QREPR = OFF_QA    + SZ_H;
constexpr long OFF_VEMB1 = OFF_QREPR + SZ_H;
constexpr long OFF_VEMB2 = OFF_VEMB1 + SZ_C;
constexpr long OFF_VREPR1= OFF_VEMB2 + SZ_C;
constexpr long OFF_VREPRV= OFF_VREPR1+ SZ_H;
constexpr long OFF_OUT   = OFF_VREPRV+ SZ_H;
constexpr long OFF_OUTV  = OFF_OUT   + SZ_H;
constexpr long OFF_QH    = OFF_OUTV  + SZ_H;
constexpr long OFF_KH    = OFF_QH    + SZ_H;
constexpr long OFF_VH    = OFF_KH    + SZ_H;
constexpr long OFF_CTX   = OFF_VH    + SZ_H;
constexpr long OFF_NEIGH = OFF_CTX   + SZ_H;
constexpr long OFF_CAT   = OFF_NEIGH + SZ_H;
constexpr long OFF_UQ    = OFF_CAT   + SZ_CAT;
constexpr long OFF_QA2   = OFF_UQ    + SZ_H;
constexpr long OFF_QREPR2= OFF_QA2   + SZ_H;
constexpr long OFF_VEMB3 = OFF_QREPR2+ SZ_H;
constexpr long OFF_VREPR2= OFF_VEMB3 + SZ_C;
constexpr long OFF_OUT2  = OFF_VREPR2+ SZ_H;
constexpr long OFF_OUTF  = OFF_OUT2  + SZ_H;
constexpr long SCRATCH_TOTAL = OFF_OUTF + SZ_H;

__device__ float g_scratch[SCRATCH_TOTAL];

// ---------------------------------------------------------------------------
// Generic SGEMM: C[M,N] = act(A[M,K] @ B[K,N] + bias)
// A/C can live in g_scratch (pass nullptr + offset) or be external pointers.
// 128x128 tile, BK=16, 256 threads, 8x8 per-thread microtile.
// ---------------------------------------------------------------------------
__global__ __launch_bounds__(256) void sgemm_kernel(
    const float* __restrict__ Aptr, long offA,
    const float* __restrict__ Bw,
    const float* __restrict__ bias,
    float* Cptr, long offC,
    int M, int N, int K, int act)
{
    const float* A = Aptr ? Aptr : (const float*)(g_scratch + offA);
    float*       C = Cptr ? Cptr : (g_scratch + offC);

    constexpr int BM = 128, BN = 128, BK = 16;
    __shared__ float As[BK][BM + 4];   // +4 pad: break stride-128 write conflicts
    __shared__ float Bs[BK][BN];

    const int tid  = threadIdx.x;
    const int brow = blockIdx.y * BM;
    const int bcol = blockIdx.x * BN;
    const int tr   = tid >> 4;         // 0..15
    const int tc   = tid & 15;         // 0..15

    float acc[8][8];
#pragma unroll
    for (int i = 0; i < 8; i++)
#pragma unroll
        for (int j = 0; j < 8; j++) acc[i][j] = 0.f;

    for (int k0 = 0; k0 < K; k0 += BK) {
#pragma unroll
        for (int l = 0; l < 8; l++) {
            int i = tid + l * 256;         // 0..2047
            int r = i >> 4, c = i & 15;
            int gr = brow + r, gc = k0 + c;
            As[c][r] = (gr < M && gc < K) ? A[(size_t)gr * K + gc] : 0.f;
        }
#pragma unroll
        for (int l = 0; l < 8; l++) {
            int i = tid + l * 256;
            int r = i >> 7, c = i & 127;
            int gr = k0 + r, gc = bcol + c;
            Bs[r][c] = (gr < K && gc < N) ? Bw[(size_t)gr * N + gc] : 0.f;
        }
        __syncthreads();

#pragma unroll
        for (int kk = 0; kk < BK; kk++) {
            float a[8], bb[8];
#pragma unroll
            for (int i = 0; i < 8; i++) a[i]  = As[kk][tr * 8 + i];
#pragma unroll
            for (int j = 0; j < 8; j++) bb[j] = Bs[kk][tc * 8 + j];
#pragma unroll
            for (int i = 0; i < 8; i++)
#pragma unroll
                for (int j = 0; j < 8; j++)
                    acc[i][j] = fmaf(a[i], bb[j], acc[i][j]);
        }
        __syncthreads();
    }

#pragma unroll
    for (int i = 0; i < 8; i++) {
        int gr = brow + tr * 8 + i;
        if (gr >= M) continue;
#pragma unroll
        for (int j = 0; j < 8; j++) {
            int gc = bcol + tc * 8 + j;
            if (gc >= N) continue;
            float v = acc[i][j];
            if (bias) v += bias[gc];
            if (act)  v = fmaxf(v, 0.f);
            C[(size_t)gr * N + gc] = v;
        }
    }
}

static inline void sgemm(const float* A, long offA, const float* Bw,
                         const float* bias, float* Cp, long offC,
                         int M, int N, int K, int act)
{
    dim3 grid((N + 127) / 128, (M + 127) / 128);
    sgemm_kernel<<<grid, 256>>>(A, offA, Bw, bias, Cp, offC, M, N, K, act);
}

// ---------------------------------------------------------------------------
// img0[b,k,c] = v_org[b,c,k]
// ---------------------------------------------------------------------------
__global__ void transpose_kernel(const float* __restrict__ v_org)
{
    long idx = (long)blockIdx.x * 256 + threadIdx.x;
    if (idx >= SZ_IMG0) return;
    int  c = (int)(idx % C_);
    long t = idx / C_;
    int  k = (int)(t % K_);
    int  b = (int)(t / K_);
    g_scratch[OFF_IMG0 + idx] = v_org[((long)b * C_ + c) * K_ + k];
}

// ---------------------------------------------------------------------------
// rv[n, 0:300] = verb_table[gt_verb[b]], rv[n, 300:600] = role_table[role_idx[n]]
// ---------------------------------------------------------------------------
__global__ void gather_rv_kernel(const int* __restrict__ gt_verb,
                                 const int* __restrict__ role_idx,
                                 const float* __restrict__ vt,
                                 const float* __restrict__ rt)
{
    long idx = (long)blockIdx.x * 256 + threadIdx.x;
    if (idx >= SZ_RV) return;
    int e = (int)(idx % TWO_E);
    int n = (int)(idx / TWO_E);
    int b = n / R_;
    float val = (e < E_) ? vt[(long)gt_verb[b] * E_ + e]
                         : rt[(long)role_idx[n] * E_ + (e - E_)];
    g_scratch[OFF_RV + idx] = val;
}

// ---------------------------------------------------------------------------
// Visual attention (one block per n in [0, BR)):
//   qa[h]     = qA[n,h] * ao_W[h]
//   logit[k]  = dot(V[b,k,:], qa) + ao_b
//   att       = softmax_k(logit)
//   vemb[n,c] = sum_k att[k] * img[b,k,c]
// ---------------------------------------------------------------------------
__global__ void att_kernel(long offV, long offQA,
                           const float* __restrict__ aoW,
                           const float* __restrict__ aoB,
                           const float* __restrict__ imgPtr, long offImg,
                           long offOut)
{
    int n = blockIdx.x;
    int b = n / R_;
    const float* V   = g_scratch + offV  + (long)b * K_ * H_;
    const float* qA  = g_scratch + offQA + (long)n * H_;
    const float* img = imgPtr ? (imgPtr + (long)b * K_ * C_)
                              : (g_scratch + offImg + (long)b * K_ * C_);
    float* out = g_scratch + offOut + (long)n * C_;

    __shared__ float qa[H_];
    __shared__ float logit[K_];
    __shared__ float attw[K_];

    int tid = threadIdx.x, wid = tid >> 5, lane = tid & 31;
    for (int h = tid; h < H_; h += 256) qa[h] = qA[h] * aoW[h];
    __syncthreads();

    for (int k = wid; k < K_; k += 8) {
        const float* vk = V + (long)k * H_;
        float s = 0.f;
        for (int h = lane; h < H_; h += 32) s = fmaf(vk[h], qa[h], s);
#pragma unroll
        for (int o = 16; o; o >>= 1) s += __shfl_xor_sync(0xffffffffu, s, o);
        if (lane == 0) logit[k] = s + aoB[0];
    }
    __syncthreads();

    float mx = -1e30f;
    for (int k = 0; k < K_; k++) mx = fmaxf(mx, logit[k]);
    float sum = 0.f;
    for (int k = 0; k < K_; k++) sum += expf(logit[k] - mx);
    if (tid < K_) attw[tid] = expf(logit[tid] - mx) / sum;
    __syncthreads();

    for (int c = tid; c < C_; c += 256) {
        float acc = 0.f;
#pragma unroll 7
        for (int k = 0; k < K_; k++)
            acc = fmaf(attw[k], img[(long)k * C_ + c], acc);
        out[c] = acc;
    }
}

// ---------------------------------------------------------------------------
// MFB pool: z = q*v ; s = sign-sqrt(z) ; out = s / max(||s||_2, 1e-12)
// One block per row.
// ---------------------------------------------------------------------------
__global__ void mfb_kernel(long offQ, long offV, long offOut)
{
    int n = blockIdx.x;
    const float* q = g_scratch + offQ   + (long)n * H_;
    const float* v = g_scratch + offV   + (long)n * H_;
    float*       o = g_scratch + offOut + (long)n * H_;
    int tid = threadIdx.x;

    float s = 0.f;
    for (int h = tid; h < H_; h += 256) {
        float z = q[h] * v[h];
        s += fabsf(z);                 // s_h^2 == |z| exactly in real math
    }
    __shared__ float red[8];
#pragma unroll
    for (int off = 16; off; off >>= 1) s += __shfl_xor_sync(0xffffffffu, s, off);
    if ((tid & 31) == 0) red[tid >> 5] = s;
    __syncthreads();
    float tot = 0.f;
#pragma unroll
    for (int i = 0; i < 8; i++) tot += red[i];
    float inv = 1.f / fmaxf(sqrtf(tot), 1e-12f);

    for (int h = tid; h < H_; h += 256) {
        float z = q[h] * v[h];
        float sg = (z > 0.f) ? sqrtf(z) : -sqrtf(-z);
        o[h] = sg * inv;
    }
}

// ---------------------------------------------------------------------------
// Masked role attention (single head), one block per batch element b.
//   scores[i,j] = dot(qh[i], kh[j]) / 32 ; diag + masked -> -1e9 ; softmax_j
//   ctx[i,:]    = sum_j attn[i,j] * vh[j,:]
// ---------------------------------------------------------------------------
__global__ void role_att_kernel(const int* __restrict__ mask)
{
    int b = blockIdx.x;
    const float* qh = g_scratch + OFF_QH + (long)b * R_ * H_;
    const float* kh = g_scratch + OFF_KH + (long)b * R_ * H_;
    const float* vh = g_scratch + OFF_VH + (long)b * R_ * H_;
    float*      ctx = g_scratch + OFF_CTX + (long)b * R_ * H_;

    __shared__ float sc[R_][R_];
    __shared__ float attn[R_][R_];
    int tid = threadIdx.x, wid = tid >> 5, lane = tid & 31;

    for (int p = wid; p < R_ * R_; p += 8) {
        int i = p / R_, j = p % R_;
        float s = 0.f;
        for (int h = lane; h < H_; h += 32)
            s = fmaf(qh[i * H_ + h], kh[j * H_ + h], s);
#pragma unroll
        for (int o = 16; o; o >>= 1) s += __shfl_xor_sync(0xffffffffu, s, o);
        if (lane == 0) {
            bool valid = (i != j) && (mask[((long)b * R_ + i) * R_ + j] > 0);
            sc[i][j] = valid ? s * (1.f / 32.f) : -1e9f;
        }
    }
    __syncthreads();

    if (tid < R_ * R_) {
        int i = tid / R_, j = tid % R_;
        float mx = -1e30f;
        for (int jj = 0; jj < R_; jj++) mx = fmaxf(mx, sc[i][jj]);
        float sum = 0.f;
        for (int jj = 0; jj < R_; jj++) sum += expf(sc[i][jj] - mx);
        attn[i][j] = expf(sc[i][j] - mx) / sum;
    }
    __syncthreads();

    for (int idx = tid; idx < R_ * H_; idx += 256) {
        int i = idx / H_, h = idx % H_;
        float acc = 0.f;
#pragma unroll
        for (int j = 0; j < R_; j++)
            acc = fmaf(attn[i][j], vh[j * H_ + h], acc);
        ctx[idx] = acc;
    }
}

// ---------------------------------------------------------------------------
// cat = [neigh | rv]
// ---------------------------------------------------------------------------
__global__ void concat_kernel()
{
    long idx = (long)blockIdx.x * 256 + threadIdx.x;
    if (idx >= SZ_CAT) return;
    int col = (int)(idx % CATW);
    int n   = (int)(idx / CATW);
    float v = (col < H_) ? g_scratch[OFF_NEIGH + (long)n * H_ + col]
                         : g_scratch[OFF_RV + (long)n * TWO_E + (col - H_)];
    g_scratch[OFF_CAT + idx] = v;
}

// ---------------------------------------------------------------------------
// gate = sigmoid(out2 + out_verb)
// out_f = (1-gate)*out_verb + gate*tanh(out2 + ans0)
// ---------------------------------------------------------------------------
__global__ void combine_kernel()
{
    long idx = (long)blockIdx.x * 256 + threadIdx.x;
    if (idx >= SZ_H) return;
    float o2 = g_scratch[OFF_OUT2 + idx];
    float ov = g_scratch[OFF_OUTV + idx];
    float a0 = g_scratch[OFF_OUT + idx];
    float g  = 1.f / (1.f + expf(-(o2 + ov)));
    g_scratch[OFF_OUTF + idx] = (1.f - g) * ov + g * tanhf(o2 + a0);
}

// ---------------------------------------------------------------------------
// Launch sequence
// ---------------------------------------------------------------------------
extern "C" void kernel_launch(void* const* d_in, const int* in_sizes, int n_in,
                              void* d_out, int out_size)
{
    const float* v_org    = (const float*)d_in[0];
    const float* img_feat = (const float*)d_in[1];
    const int*   gt_verb  = (const int*)d_in[2];
    const int*   role_idx = (const int*)d_in[3];
    const int*   mask     = (const int*)d_in[4];
    const float* verb_t   = (const float*)d_in[5];
    const float* role_t   = (const float*)d_in[6];
    const float* qc_W = (const float*)d_in[7];   const float* qc_b = (const float*)d_in[8];
    const float* av_W = (const float*)d_in[9];   const float* av_b = (const float*)d_in[10];
    const float* aq_W = (const float*)d_in[11];  const float* aq_b = (const float*)d_in[12];
    const float* ao_W = (const float*)d_in[13];  const float* ao_b = (const float*)d_in[14];
    const float* vn_W = (const float*)d_in[15];  const float* vn_b = (const float*)d_in[16];
    const float* qn_W = (const float*)d_in[17];  const float* qn_b = (const float*)d_in[18];
    const float* Wq   = (const float*)d_in[19];
    const float* Wk   = (const float*)d_in[20];
    const float* Wv   = (const float*)d_in[21];
    const float* Wo   = (const float*)d_in[22];
    const float* uqc_W = (const float*)d_in[23]; const float* uqc_b = (const float*)d_in[24];
    const float* cls_W = (const float*)d_in[25]; const float* cls_b = (const float*)d_in[26];

    // prep
    transpose_kernel<<<(int)((SZ_IMG0 + 255) / 256), 256>>>(v_org);
    gather_rv_kernel<<<(int)((SZ_RV + 255) / 256), 256>>>(gt_verb, role_idx, verb_t, role_t);

    // image value projections (computed ONCE, reused by all 3 attention calls)
    sgemm(nullptr, OFF_IMG0, av_W, av_b, nullptr, OFF_V1, B_ * K_, H_, C_, 1);
    sgemm(img_feat, 0,       av_W, av_b, nullptr, OFF_V2, B_ * K_, H_, C_, 1);

    // query chain
    sgemm(nullptr, OFF_RV,   qc_W, qc_b, nullptr, OFF_QEMB,  BR_, H_, TWO_E, 1);
    sgemm(nullptr, OFF_QEMB, aq_W, aq_b, nullptr, OFF_QA,    BR_, H_, H_,    1);
    sgemm(nullptr, OFF_QEMB, qn_W, qn_b, nullptr, OFF_QREPR, BR_, H_, H_,    1);

    // attention 1 (spatial image) and attention-verb (img_feat)
    att_kernel<<<BR_, 256>>>(OFF_V1, OFF_QA, ao_W, ao_b, nullptr,  OFF_IMG0, OFF_VEMB1);
    att_kernel<<<BR_, 256>>>(OFF_V2, OFF_QA, ao_W, ao_b, img_feat, 0,        OFF_VEMB2);

    sgemm(nullptr, OFF_VEMB1, vn_W, vn_b, nullptr, OFF_VREPR1, BR_, H_, C_, 1);
    sgemm(nullptr, OFF_VEMB2, vn_W, vn_b, nullptr, OFF_VREPRV, BR_, H_, C_, 1);

    mfb_kernel<<<BR_, 256>>>(OFF_QREPR, OFF_VREPR1, OFF_OUT);
    mfb_kernel<<<BR_, 256>>>(OFF_QREPR, OFF_VREPRV, OFF_OUTV);

    // role-node neighbour attention
    sgemm(nullptr, OFF_OUT, Wq, nullptr, nullptr, OFF_QH, BR_, H_, H_, 0);
    sgemm(nullptr, OFF_OUT, Wk, nullptr, nullptr, OFF_KH, BR_, H_, H_, 0);
    sgemm(nullptr, OFF_OUT, Wv, nullptr, nullptr, OFF_VH, BR_, H_, H_, 0);
    role_att_kernel<<<B_, 256>>>(mask);
    sgemm(nullptr, OFF_CTX, Wo, nullptr, nullptr, OFF_NEIGH, BR_, H_, H_, 0);

    // updated query
    concat_kernel<<<(int)((SZ_CAT + 255) / 256), 256>>>();
    sgemm(nullptr, OFF_CAT, uqc_W, uqc_b, nullptr, OFF_UQ,     BR_, H_, CATW, 1);
    sgemm(nullptr, OFF_UQ,  aq_W,  aq_b,  nullptr, OFF_QA2,    BR_, H_, H_,   1);
    sgemm(nullptr, OFF_UQ,  qn_W,  qn_b,  nullptr, OFF_QREPR2, BR_, H_, H_,   1);

    // attention 2 on spatial image with updated query
    att_kernel<<<BR_, 256>>>(OFF_V1, OFF_QA2, ao_W, ao_b, nullptr, OFF_IMG0, OFF_VEMB3);
    sgemm(nullptr, OFF_VEMB3, vn_W, vn_b, nullptr, OFF_VREPR2, BR_, H_, C_, 1);
    mfb_kernel<<<BR_, 256>>>(OFF_QREPR2, OFF_VREPR2, OFF_OUT2);

    // gated fusion
    combine_kernel<<<(int)((SZ_H + 255) / 256), 256>>>();

    // classifier -> d_out
    sgemm(nullptr, OFF_OUTF, cls_W, cls_b, (float*)d_out, 0, BR_, NL_, H_, 0);
}

// round 2
// speedup vs baseline: 1.1422x; 1.1422x over previous
#include <cuda_runtime.h>
#include <cstdint>
#include <math.h>

typedef unsigned long long ull;

// ---------------------------------------------------------------------------
// Problem dims
// ---------------------------------------------------------------------------
constexpr int B_   = 256;
constexpr int R_   = 6;
constexpr int K_   = 49;
constexpr int C_   = 512;
constexpr int H_   = 1024;
constexpr int E_   = 300;
constexpr int BR_  = B_ * R_;          // 1536
constexpr int NL_  = 2001;
constexpr int TWO_E = 2 * E_;          // 600
constexpr int CATW  = H_ + TWO_E;      // 1624

// ---------------------------------------------------------------------------
// Scratch layout (single __device__ buffer, constexpr offsets)
// ---------------------------------------------------------------------------
constexpr long SZ_IMG0 = (long)B_ * K_ * C_;
constexpr long SZ_V    = (long)B_ * K_ * H_;
constexpr long SZ_RV   = (long)BR_ * TWO_E;
constexpr long SZ_H    = (long)BR_ * H_;
constexpr long SZ_C    = (long)BR_ * C_;
constexpr long SZ_CAT  = (long)BR_ * CATW;

constexpr long OFF_IMG0  = 0;
constexpr long OFF_V1    = OFF_IMG0  + SZ_IMG0;
constexpr long OFF_V2    = OFF_V1    + SZ_V;
constexpr long OFF_RV    = OFF_V2    + SZ_V;
constexpr long OFF_QEMB  = OFF_RV    + SZ_RV;
constexpr long OFF_QA    = OFF_QEMB  + SZ_H;
constexpr long OFF_QREPR = OFF_QA    + SZ_H;
constexpr long OFF_VEMB1 = OFF_QREPR + SZ_H;
constexpr long OFF_VEMB2 = OFF_VEMB1 + SZ_C;
constexpr long OFF_VREPR1= OFF_VEMB2 + SZ_C;
constexpr long OFF_VREPRV= OFF_VREPR1+ SZ_H;
constexpr long OFF_OUT   = OFF_VREPRV+ SZ_H;
constexpr long OFF_OUTV  = OFF_OUT   + SZ_H;
constexpr long OFF_QH    = OFF_OUTV  + SZ_H;
constexpr long OFF_KH    = OFF_QH    + SZ_H;
constexpr long OFF_VH    = OFF_KH    + SZ_H;
constexpr long OFF_CTX   = OFF_VH    + SZ_H;
constexpr long OFF_NEIGH = OFF_CTX   + SZ_H;
constexpr long OFF_CAT   = OFF_NEIGH + SZ_H;
constexpr long OFF_UQ    = OFF_CAT   + SZ_CAT;
constexpr long OFF_QA2   = OFF_UQ    + SZ_H;
constexpr long OFF_QREPR2= OFF_QA2   + SZ_H;
constexpr long OFF_VEMB3 = OFF_QREPR2+ SZ_H;
constexpr long OFF_VREPR2= OFF_VEMB3 + SZ_C;
constexpr long OFF_OUT2  = OFF_VREPR2+ SZ_H;
constexpr long OFF_OUTF  = OFF_OUT2  + SZ_H;
constexpr long SCRATCH_TOTAL = OFF_OUTF + SZ_H;

__device__ float g_scratch[SCRATCH_TOTAL];

// ---------------------------------------------------------------------------
// Packed fp32x2 helpers (Blackwell FFMA2 path — exact fp32 semantics)
// ---------------------------------------------------------------------------
__device__ __forceinline__ ull pk2(float x, float y) {
    ull r; asm("mov.b64 %0, {%1, %2};" : "=l"(r) : "f"(x), "f"(y)); return r;
}
__device__ __forceinline__ float2 upk2(ull v) {
    float2 f; asm("mov.b64 {%0, %1}, %2;" : "=f"(f.x), "=f"(f.y) : "l"(v)); return f;
}
__device__ __forceinline__ void ffma2(ull& d, ull a, ull b) {
    asm("fma.rn.f32x2 %0, %1, %2, %0;" : "+l"(d) : "l"(a), "l"(b));
}

// ---------------------------------------------------------------------------
// SGEMM: C[M,N] = act(A[M,K] @ B[K,N] + bias), packed-FFMA2 inner loop.
// BM x 128 tile, BK=16, 256 threads, TM x 8 per-thread microtile.
// Requires: M % BM == 0, K % 4 == 0 (true for all call sites).
// Double-buffered smem, float4 global loads (scalar fallback when N%4 != 0).
// ---------------------------------------------------------------------------
template<int BM, int TM>
__global__ __launch_bounds__(256, 2) void sgemm2_kernel(
    const float* __restrict__ Aptr, long offA,
    const float* __restrict__ Bw,
    const float* __restrict__ bias,
    float* Cptr, long offC,
    int M, int N, int K, int act)
{
    constexpr int BN = 128, BK = 16;
    constexpr int AS = BM + 2;          // stride 130/66: conflict-free scatter
    const float* A = Aptr ? Aptr : (const float*)(g_scratch + offA);
    float*       C = Cptr ? Cptr : (g_scratch + offC);

    __shared__ __align__(16) float As[2][BK][AS];
    __shared__ __align__(16) float Bs[2][BK][BN];

    const int tid  = threadIdx.x;
    const int brow = blockIdx.y * BM;
    const int bcol = blockIdx.x * BN;
    const int tr   = tid >> 4;          // 0..15
    const int tc   = tid & 15;          // 0..15

    const bool nvec = ((N & 3) == 0) && (bcol + BN <= N);

    float4 aReg[BM / 64];
    float4 bReg[2];
    float  bRegS[8];

    auto ldA = [&](int k0) {
#pragma unroll
        for (int l = 0; l < BM / 64; l++) {
            int idx = tid + l * 256;
            int arow = idx >> 2, akq = idx & 3;
            int gk = k0 + akq * 4;
            if (gk < K) aReg[l] = *(const float4*)&A[(size_t)(brow + arow) * K + gk];
            else        aReg[l] = make_float4(0.f, 0.f, 0.f, 0.f);
        }
    };
    auto stA = [&](int buf) {
#pragma unroll
        for (int l = 0; l < BM / 64; l++) {
            int idx = tid + l * 256;
            int arow = idx >> 2, akq = idx & 3;
            As[buf][akq * 4 + 0][arow] = aReg[l].x;
            As[buf][akq * 4 + 1][arow] = aReg[l].y;
            As[buf][akq * 4 + 2][arow] = aReg[l].z;
            As[buf][akq * 4 + 3][arow] = aReg[l].w;
        }
    };
    auto ldB = [&](int k0) {
        if (nvec) {
#pragma unroll
            for (int l = 0; l < 2; l++) {
                int idx = tid + l * 256;
                int br = idx >> 5, bc4 = idx & 31;
                int gk = k0 + br;
                if (gk < K) bReg[l] = *(const float4*)&Bw[(size_t)gk * N + bcol + bc4 * 4];
                else        bReg[l] = make_float4(0.f, 0.f, 0.f, 0.f);
            }
        } else {
#pragma unroll
            for (int l = 0; l < 8; l++) {
                int idx = tid + l * 256;
                int br = idx >> 7, bc = idx & 127;
                int gk = k0 + br, gc = bcol + bc;
                bRegS[l] = (gk < K && gc < N) ? Bw[(size_t)gk * N + gc] : 0.f;
            }
        }
    };
    auto stB = [&](int buf) {
        if (nvec) {
#pragma unroll
            for (int l = 0; l < 2; l++) {
                int idx = tid + l * 256;
                int br = idx >> 5, bc4 = idx & 31;
                *(float4*)&Bs[buf][br][bc4 * 4] = bReg[l];
            }
        } else {
#pragma unroll
            for (int l = 0; l < 8; l++) {
                int idx = tid + l * 256;
                int br = idx >> 7, bc = idx & 127;
                Bs[buf][br][bc] = bRegS[l];
            }
        }
    };

    ull acc[TM][4];
#pragma unroll
    for (int i = 0; i < TM; i++)
#pragma unroll
        for (int j = 0; j < 4; j++) acc[i][j] = 0ULL;

    ldA(0); ldB(0);
    stA(0); stB(0);
    __syncthreads();

    const int nTiles = (K + BK - 1) / BK;
    for (int t = 0; t < nTiles; t++) {
        int cur = t & 1, nxt = cur ^ 1;
        if (t + 1 < nTiles) { ldA((t + 1) * BK); ldB((t + 1) * BK); }

#pragma unroll
        for (int kk = 0; kk < BK; kk++) {
            const ull* ar2 = (const ull*)&As[cur][kk][tr * TM];
            const ull* br2 = (const ull*)&Bs[cur][kk][tc * 8];
            ull bv[4];
#pragma unroll
            for (int j = 0; j < 4; j++) bv[j] = br2[j];
#pragma unroll
            for (int i2 = 0; i2 < TM / 2; i2++) {
                float2 ap = upk2(ar2[i2]);
                ull ad0 = pk2(ap.x, ap.x);
                ull ad1 = pk2(ap.y, ap.y);
#pragma unroll
                for (int j = 0; j < 4; j++) ffma2(acc[2 * i2 + 0][j], ad0, bv[j]);
#pragma unroll
                for (int j = 0; j < 4; j++) ffma2(acc[2 * i2 + 1][j], ad1, bv[j]);
            }
        }

        if (t + 1 < nTiles) { stA(nxt); stB(nxt); }
        __syncthreads();
    }

    // epilogue (M % BM == 0 guaranteed — only N needs guarding)
#pragma unroll
    for (int i = 0; i < TM; i++) {
        int gr = brow + tr * TM + i;
#pragma unroll
        for (int j = 0; j < 4; j++) {
            int gc = bcol + tc * 8 + 2 * j;
            float2 v = upk2(acc[i][j]);
            if (nvec) {
                if (bias) { v.x += bias[gc]; v.y += bias[gc + 1]; }
                if (act)  { v.x = fmaxf(v.x, 0.f); v.y = fmaxf(v.y, 0.f); }
                *(float2*)&C[(size_t)gr * N + gc] = v;
            } else {
                if (gc < N) {
                    float o = v.x + (bias ? bias[gc] : 0.f);
                    if (act) o = fmaxf(o, 0.f);
                    C[(size_t)gr * N + gc] = o;
                }
                if (gc + 1 < N) {
                    float o = v.y + (bias ? bias[gc + 1] : 0.f);
                    if (act) o = fmaxf(o, 0.f);
                    C[(size_t)gr * N + gc + 1] = o;
                }
            }
        }
    }
}

static inline void sgemm(const float* A, long offA, const float* Bw,
                         const float* bias, float* Cp, long offC,
                         int M, int N, int K, int act)
{
    if (M >= 4096) {
        dim3 grid((N + 127) / 128, M / 128);
        sgemm2_kernel<128, 8><<<grid, 256>>>(A, offA, Bw, bias, Cp, offC, M, N, K, act);
    } else {
        dim3 grid((N + 127) / 128, M / 64);
        sgemm2_kernel<64, 4><<<grid, 256>>>(A, offA, Bw, bias, Cp, offC, M, N, K, act);
    }
}

// ---------------------------------------------------------------------------
// img0[b,k,c] = v_org[b,c,k]
// ---------------------------------------------------------------------------
__global__ void transpose_kernel(const float* __restrict__ v_org)
{
    long idx = (long)blockIdx.x * 256 + threadIdx.x;
    if (idx >= SZ_IMG0) return;
    int  c = (int)(idx % C_);
    long t = idx / C_;
    int  k = (int)(t % K_);
    int  b = (int)(t / K_);
    g_scratch[OFF_IMG0 + idx] = v_org[((long)b * C_ + c) * K_ + k];
}

// ---------------------------------------------------------------------------
// rv[n, 0:300] = verb_table[gt_verb[b]], rv[n, 300:600] = role_table[role_idx[n]]
// ---------------------------------------------------------------------------
__global__ void gather_rv_kernel(const int* __restrict__ gt_verb,
                                 const int* __restrict__ role_idx,
                                 const float* __restrict__ vt,
                                 const float* __restrict__ rt)
{
    long idx = (long)blockIdx.x * 256 + threadIdx.x;
    if (idx >= SZ_RV) return;
    int e = (int)(idx % TWO_E);
    int n = (int)(idx / TWO_E);
    int b = n / R_;
    float val = (e < E_) ? vt[(long)gt_verb[b] * E_ + e]
                         : rt[(long)role_idx[n] * E_ + (e - E_)];
    g_scratch[OFF_RV + idx] = val;
}

// ---------------------------------------------------------------------------
// Visual attention (one block per n in [0, BR)):
//   qa[h]     = qA[n,h] * ao_W[h]
//   logit[k]  = dot(V[b,k,:], qa) + ao_b
//   att       = softmax_k(logit)
//   vemb[n,c] = sum_k att[k] * img[b,k,c]
// ---------------------------------------------------------------------------
__global__ void att_kernel(long offV, long offQA,
                           const float* __restrict__ aoW,
                           const float* __restrict__ aoB,
                           const float* __restrict__ imgPtr, long offImg,
                           long offOut)
{
    int n = blockIdx.x;
    int b = n / R_;
    const float* V   = g_scratch + offV  + (long)b * K_ * H_;
    const float* qA  = g_scratch + offQA + (long)n * H_;
    const float* img = imgPtr ? (imgPtr + (long)b * K_ * C_)
                              : (g_scratch + offImg + (long)b * K_ * C_);
    float* out = g_scratch + offOut + (long)n * C_;

    __shared__ float qa[H_];
    __shared__ float logit[K_];
    __shared__ float attw[K_];

    int tid = threadIdx.x, wid = tid >> 5, lane = tid & 31;
    for (int h = tid; h < H_; h += 256) qa[h] = qA[h] * aoW[h];
    __syncthreads();

    for (int k = wid; k < K_; k += 8) {
        const float* vk = V + (long)k * H_;
        float s = 0.f;
        for (int h = lane; h < H_; h += 32) s = fmaf(vk[h], qa[h], s);
#pragma unroll
        for (int o = 16; o; o >>= 1) s += __shfl_xor_sync(0xffffffffu, s, o);
        if (lane == 0) logit[k] = s + aoB[0];
    }
    __syncthreads();

    float mx = -1e30f;
    for (int k = 0; k < K_; k++) mx = fmaxf(mx, logit[k]);
    float sum = 0.f;
    for (int k = 0; k < K_; k++) sum += expf(logit[k] - mx);
    if (tid < K_) attw[tid] = expf(logit[tid] - mx) / sum;
    __syncthreads();

    for (int c = tid; c < C_; c += 256) {
        float acc = 0.f;
#pragma unroll 7
        for (int k = 0; k < K_; k++)
            acc = fmaf(attw[k], img[(long)k * C_ + c], acc);
        out[c] = acc;
    }
}

// ---------------------------------------------------------------------------
// MFB pool: z = q*v ; s = sign-sqrt(z) ; out = s / max(||s||_2, 1e-12)
// ---------------------------------------------------------------------------
__global__ void mfb_kernel(long offQ, long offV, long offOut)
{
    int n = blockIdx.x;
    const float* q = g_scratch + offQ   + (long)n * H_;
    const float* v = g_scratch + offV   + (long)n * H_;
    float*       o = g_scratch + offOut + (long)n * H_;
    int tid = threadIdx.x;

    float s = 0.f;
    for (int h = tid; h < H_; h += 256) {
        float z = q[h] * v[h];
        s += fabsf(z);
    }
    __shared__ float red[8];
#pragma unroll
    for (int off = 16; off; off >>= 1) s += __shfl_xor_sync(0xffffffffu, s, off);
    if ((tid & 31) == 0) red[tid >> 5] = s;
    __syncthreads();
    float tot = 0.f;
#pragma unroll
    for (int i = 0; i < 8; i++) tot += red[i];
    float inv = 1.f / fmaxf(sqrtf(tot), 1e-12f);

    for (int h = tid; h < H_; h += 256) {
        float z = q[h] * v[h];
        float sg = (z > 0.f) ? sqrtf(z) : -sqrtf(-z);
        o[h] = sg * inv;
    }
}

// ---------------------------------------------------------------------------
// Masked role attention (single head), one block per batch element b.
// ---------------------------------------------------------------------------
__global__ void role_att_kernel(const int* __restrict__ mask)
{
    int b = blockIdx.x;
    const float* qh = g_scratch + OFF_QH + (long)b * R_ * H_;
    const float* kh = g_scratch + OFF_KH + (long)b * R_ * H_;
    const float* vh = g_scratch + OFF_VH + (long)b * R_ * H_;
    float*      ctx = g_scratch + OFF_CTX + (long)b * R_ * H_;

    __shared__ float sc[R_][R_];
    __shared__ float attn[R_][R_];
    int tid = threadIdx.x, wid = tid >> 5, lane = tid & 31;

    for (int p = wid; p < R_ * R_; p += 8) {
        int i = p / R_, j = p % R_;
        float s = 0.f;
        for (int h = lane; h < H_; h += 32)
            s = fmaf(qh[i * H_ + h], kh[j * H_ + h], s);
#pragma unroll
        for (int o = 16; o; o >>= 1) s += __shfl_xor_sync(0xffffffffu, s, o);
        if (lane == 0) {
            bool valid = (i != j) && (mask[((long)b * R_ + i) * R_ + j] > 0);
            sc[i][j] = valid ? s * (1.f / 32.f) : -1e9f;
        }
    }
    __syncthreads();

    if (tid < R_ * R_) {
        int i = tid / R_, j = tid % R_;
        float mx = -1e30f;
        for (int jj = 0; jj < R_; jj++) mx = fmaxf(mx, sc[i][jj]);
        float sum = 0.f;
        for (int jj = 0; jj < R_; jj++) sum += expf(sc[i][jj] - mx);
        attn[i][j] = expf(sc[i][j] - mx) / sum;
    }
    __syncthreads();

    for (int idx = tid; idx < R_ * H_; idx += 256) {
        int i = idx / H_, h = idx % H_;
        float acc = 0.f;
#pragma unroll
        for (int j = 0; j < R_; j++)
            acc = fmaf(attn[i][j], vh[j * H_ + h], acc);
        ctx[idx] = acc;
    }
}

// ---------------------------------------------------------------------------
// cat = [neigh | rv]
// ---------------------------------------------------------------------------
__global__ void concat_kernel()
{
    long idx = (long)blockIdx.x * 256 + threadIdx.x;
    if (idx >= SZ_CAT) return;
    int col = (int)(idx % CATW);
    int n   = (int)(idx / CATW);
    float v = (col < H_) ? g_scratch[OFF_NEIGH + (long)n * H_ + col]
                         : g_scratch[OFF_RV + (long)n * TWO_E + (col - H_)];
    g_scratch[OFF_CAT + idx] = v;
}

// ---------------------------------------------------------------------------
// gate = sigmoid(out2 + out_verb); out_f = (1-gate)*out_verb + gate*tanh(out2+ans0)
// ---------------------------------------------------------------------------
__global__ void combine_kernel()
{
    long idx = (long)blockIdx.x * 256 + threadIdx.x;
    if (idx >= SZ_H) return;
    float o2 = g_scratch[OFF_OUT2 + idx];
    float ov = g_scratch[OFF_OUTV + idx];
    float a0 = g_scratch[OFF_OUT + idx];
    float g  = 1.f / (1.f + expf(-(o2 + ov)));
    g_scratch[OFF_OUTF + idx] = (1.f - g) * ov + g * tanhf(o2 + a0);
}

// ---------------------------------------------------------------------------
// Launch sequence
// ---------------------------------------------------------------------------
extern "C" void kernel_launch(void* const* d_in, const int* in_sizes, int n_in,
                              void* d_out, int out_size)
{
    const float* v_org    = (const float*)d_in[0];
    const float* img_feat = (const float*)d_in[1];
    const int*   gt_verb  = (const int*)d_in[2];
    const int*   role_idx = (const int*)d_in[3];
    const int*   mask     = (const int*)d_in[4];
    const float* verb_t   = (const float*)d_in[5];
    const float* role_t   = (const float*)d_in[6];
    const float* qc_W = (const float*)d_in[7];   const float* qc_b = (const float*)d_in[8];
    const float* av_W = (const float*)d_in[9];   const float* av_b = (const float*)d_in[10];
    const float* aq_W = (const float*)d_in[11];  const float* aq_b = (const float*)d_in[12];
    const float* ao_W = (const float*)d_in[13];  const float* ao_b = (const float*)d_in[14];
    const float* vn_W = (const float*)d_in[15];  const float* vn_b = (const float*)d_in[16];
    const float* qn_W = (const float*)d_in[17];  const float* qn_b = (const float*)d_in[18];
    const float* Wq   = (const float*)d_in[19];
    const float* Wk   = (const float*)d_in[20];
    const float* Wv   = (const float*)d_in[21];
    const float* Wo   = (const float*)d_in[22];
    const float* uqc_W = (const float*)d_in[23]; const float* uqc_b = (const float*)d_in[24];
    const float* cls_W = (const float*)d_in[25]; const float* cls_b = (const float*)d_in[26];

    // prep
    transpose_kernel<<<(int)((SZ_IMG0 + 255) / 256), 256>>>(v_org);
    gather_rv_kernel<<<(int)((SZ_RV + 255) / 256), 256>>>(gt_verb, role_idx, verb_t, role_t);

    // image value projections (computed ONCE, reused by all 3 attention calls)
    sgemm(nullptr, OFF_IMG0, av_W, av_b, nullptr, OFF_V1, B_ * K_, H_, C_, 1);
    sgemm(img_feat, 0,       av_W, av_b, nullptr, OFF_V2, B_ * K_, H_, C_, 1);

    // query chain
    sgemm(nullptr, OFF_RV,   qc_W, qc_b, nullptr, OFF_QEMB,  BR_, H_, TWO_E, 1);
    sgemm(nullptr, OFF_QEMB, aq_W, aq_b, nullptr, OFF_QA,    BR_, H_, H_,    1);
    sgemm(nullptr, OFF_QEMB, qn_W, qn_b, nullptr, OFF_QREPR, BR_, H_, H_,    1);

    // attention 1 (spatial image) and attention-verb (img_feat)
    att_kernel<<<BR_, 256>>>(OFF_V1, OFF_QA, ao_W, ao_b, nullptr,  OFF_IMG0, OFF_VEMB1);
    att_kernel<<<BR_, 256>>>(OFF_V2, OFF_QA, ao_W, ao_b, img_feat, 0,        OFF_VEMB2);

    sgemm(nullptr, OFF_VEMB1, vn_W, vn_b, nullptr, OFF_VREPR1, BR_, H_, C_, 1);
    sgemm(nullptr, OFF_VEMB2, vn_W, vn_b, nullptr, OFF_VREPRV, BR_, H_, C_, 1);

    mfb_kernel<<<BR_, 256>>>(OFF_QREPR, OFF_VREPR1, OFF_OUT);
    mfb_kernel<<<BR_, 256>>>(OFF_QREPR, OFF_VREPRV, OFF_OUTV);

    // role-node neighbour attention
    sgemm(nullptr, OFF_OUT, Wq, nullptr, nullptr, OFF_QH, BR_, H_, H_, 0);
    sgemm(nullptr, OFF_OUT, Wk, nullptr, nullptr, OFF_KH, BR_, H_, H_, 0);
    sgemm(nullptr, OFF_OUT, Wv, nullptr, nullptr, OFF_VH, BR_, H_, H_, 0);
    role_att_kernel<<<B_, 256>>>(mask);
    sgemm(nullptr, OFF_CTX, Wo, nullptr, nullptr, OFF_NEIGH, BR_, H_, H_, 0);

    // updated query
    concat_kernel<<<(int)((SZ_CAT + 255) / 256), 256>>>();
    sgemm(nullptr, OFF_CAT, uqc_W, uqc_b, nullptr, OFF_UQ,     BR_, H_, CATW, 1);
    sgemm(nullptr, OFF_UQ,  aq_W,  aq_b,  nullptr, OFF_QA2,    BR_, H_, H_,   1);
    sgemm(nullptr, OFF_UQ,  qn_W,  qn_b,  nullptr, OFF_QREPR2, BR_, H_, H_,   1);

    // attention 2 on spatial image with updated query
    att_kernel<<<BR_, 256>>>(OFF_V1, OFF_QA2, ao_W, ao_b, nullptr, OFF_IMG0, OFF_VEMB3);
    sgemm(nullptr, OFF_VEMB3, vn_W, vn_b, nullptr, OFF_VREPR2, BR_, H_, C_, 1);
    mfb_kernel<<<BR_, 256>>>(OFF_QREPR2, OFF_VREPR2, OFF_OUT2);

    // gated fusion
    combine_kernel<<<(int)((SZ_H + 255) / 256), 256>>>();

    // classifier -> d_out
    sgemm(nullptr, OFF_OUTF, cls_W, cls_b, (float*)d_out, 0, BR_, NL_, H_, 0);
}

// round 4
// speedup vs baseline: 2.5931x; 2.2703x over previous
#include <cuda_runtime.h>
#include <cuda_bf16.h>
#include <cstdint>
#include <math.h>

// ---------------------------------------------------------------------------
// Problem dims
// ---------------------------------------------------------------------------
constexpr int B_   = 256;
constexpr int R_   = 6;
constexpr int K_   = 49;
constexpr int C_   = 512;
constexpr int H_   = 1024;
constexpr int E_   = 300;
constexpr int BR_  = B_ * R_;          // 1536
constexpr int NL_  = 2001;
constexpr int TWO_E = 2 * E_;          // 600
constexpr int CATW  = H_ + TWO_E;      // 1624

// ---------------------------------------------------------------------------
// fp32 scratch
// ---------------------------------------------------------------------------
constexpr long SZ_IMG0 = (long)B_ * K_ * C_;
constexpr long SZ_V    = (long)B_ * K_ * H_;
constexpr long SZ_RV   = (long)BR_ * TWO_E;
constexpr long SZ_H    = (long)BR_ * H_;
constexpr long SZ_C    = (long)BR_ * C_;
constexpr long SZ_CAT  = (long)BR_ * CATW;

constexpr long OFF_IMG0  = 0;
constexpr long OFF_V1    = OFF_IMG0  + SZ_IMG0;
constexpr long OFF_V2    = OFF_V1    + SZ_V;
constexpr long OFF_RV    = OFF_V2    + SZ_V;
constexpr long OFF_QEMB  = OFF_RV    + SZ_RV;
constexpr long OFF_QA    = OFF_QEMB  + SZ_H;
constexpr long OFF_QREPR = OFF_QA    + SZ_H;
constexpr long OFF_VEMB1 = OFF_QREPR + SZ_H;
constexpr long OFF_VEMB2 = OFF_VEMB1 + SZ_C;
constexpr long OFF_VREPR1= OFF_VEMB2 + SZ_C;
constexpr long OFF_VREPRV= OFF_VREPR1+ SZ_H;
constexpr long OFF_OUT   = OFF_VREPRV+ SZ_H;
constexpr long OFF_OUTV  = OFF_OUT   + SZ_H;
constexpr long OFF_QH    = OFF_OUTV  + SZ_H;
constexpr long OFF_KH    = OFF_QH    + SZ_H;
constexpr long OFF_VH    = OFF_KH    + SZ_H;
constexpr long OFF_CTX   = OFF_VH    + SZ_H;
constexpr long OFF_NEIGH = OFF_CTX   + SZ_H;
constexpr long OFF_CAT   = OFF_NEIGH + SZ_H;
constexpr long OFF_UQ    = OFF_CAT   + SZ_CAT;
constexpr long OFF_QA2   = OFF_UQ    + SZ_H;
constexpr long OFF_QREPR2= OFF_QA2   + SZ_H;
constexpr long OFF_VEMB3 = OFF_QREPR2+ SZ_H;
constexpr long OFF_VREPR2= OFF_VEMB3 + SZ_C;
constexpr long OFF_OUT2  = OFF_VREPR2+ SZ_H;
constexpr long OFF_OUTF  = OFF_OUT2  + SZ_H;
constexpr long SCRATCH_TOTAL = OFF_OUTF + SZ_H;

__device__ float g_scratch[SCRATCH_TOTAL];

// ---------------------------------------------------------------------------
// bf16 weight buffers (transposed [Npad][Kpad], hi at off, lo at off+WTOTAL)
// ---------------------------------------------------------------------------
constexpr long WOFF_QC  = 0;                       constexpr long WSZ_QC  = 1024L * 640;
constexpr long WOFF_AV  = WOFF_QC  + WSZ_QC;       constexpr long WSZ_AV  = 1024L * 512;
constexpr long WSZ_SQ   = 1024L * 1024;
constexpr long WOFF_AQ  = WOFF_AV  + WSZ_AV;
constexpr long WOFF_QN  = WOFF_AQ  + WSZ_SQ;
constexpr long WOFF_VN  = WOFF_QN  + WSZ_SQ;       constexpr long WSZ_VN  = 1024L * 512;
constexpr long WOFF_WQ  = WOFF_VN  + WSZ_VN;
constexpr long WOFF_WK  = WOFF_WQ  + WSZ_SQ;
constexpr long WOFF_WV  = WOFF_WK  + WSZ_SQ;
constexpr long WOFF_WO  = WOFF_WV  + WSZ_SQ;
constexpr long WOFF_UQC = WOFF_WO  + WSZ_SQ;       constexpr long WSZ_UQC = 1024L * 1664;
constexpr long WOFF_CLS = WOFF_UQC + WSZ_UQC;      constexpr long WSZ_CLS = 2048L * 1024;
constexpr long WTOTAL   = WOFF_CLS + WSZ_CLS;

__device__ __nv_bfloat16 g_wbf[2 * WTOTAL];

// ---------------------------------------------------------------------------
// helpers
// ---------------------------------------------------------------------------
__device__ __forceinline__ uint32_t smem_u32(const void* p) {
    uint32_t a;
    asm("{ .reg .u64 t; cvta.to.shared.u64 t, %1; cvt.u32.u64 %0, t; }" : "=r"(a) : "l"(p));
    return a;
}

__device__ __forceinline__ void split2(float x, float y, uint32_t& hp, uint32_t& lp) {
    __nv_bfloat16 hx = __float2bfloat16(x), hy = __float2bfloat16(y);
    __nv_bfloat16 lx = __float2bfloat16(x - __bfloat162float(hx));
    __nv_bfloat16 ly = __float2bfloat16(y - __bfloat162float(hy));
    hp = (uint32_t)__bfloat16_as_ushort(hx) | ((uint32_t)__bfloat16_as_ushort(hy) << 16);
    lp = (uint32_t)__bfloat16_as_ushort(lx) | ((uint32_t)__bfloat16_as_ushort(ly) << 16);
}

__device__ __forceinline__ void ldm_x4(uint32_t* r, uint32_t addr) {
    asm volatile("ldmatrix.sync.aligned.m8n8.x4.shared.b16 {%0,%1,%2,%3}, [%4];"
                 : "=r"(r[0]), "=r"(r[1]), "=r"(r[2]), "=r"(r[3]) : "r"(addr));
}

__device__ __forceinline__ void mma16816(float* c, const uint32_t* a, const uint32_t* b) {
    asm volatile(
        "mma.sync.aligned.m16n8k16.row.col.f32.bf16.bf16.f32 "
        "{%0,%1,%2,%3}, {%4,%5,%6,%7}, {%8,%9}, {%0,%1,%2,%3};"
        : "+f"(c[0]), "+f"(c[1]), "+f"(c[2]), "+f"(c[3])
        : "r"(a[0]), "r"(a[1]), "r"(a[2]), "r"(a[3]), "r"(b[0]), "r"(b[1]));
}

// ---------------------------------------------------------------------------
// Weight transpose + bf16 hi/lo split:  W[K,N] fp32 -> g_wbf [Npad][Kpad]
// ---------------------------------------------------------------------------
__global__ void wconv_kernel(const float* __restrict__ W,
                             int K, int N, int Kp, int Np, long off)
{
    __shared__ float tile[32][33];
    int k0 = blockIdx.x * 32, n0 = blockIdx.y * 32;
    int tx = threadIdx.x, ty = threadIdx.y;
#pragma unroll
    for (int i = 0; i < 32; i += 8) {
        int k = k0 + ty + i, n = n0 + tx;
        tile[ty + i][tx] = (k < K && n < N) ? W[(size_t)k * N + n] : 0.f;
    }
    __syncthreads();
#pragma unroll
    for (int i = 0; i < 32; i += 8) {
        int n = n0 + ty + i, k = k0 + tx;
        float v = tile[tx][ty + i];
        __nv_bfloat16 h = __float2bfloat16(v);
        __nv_bfloat16 l = __float2bfloat16(v - __bfloat162float(h));
        long o = off + (long)n * Kp + k;
        g_wbf[o] = h;
        g_wbf[o + WTOTAL] = l;
    }
}

// ---------------------------------------------------------------------------
// HMMA bf16-split GEMM: C[M,N] = act(A[M,Kact] @ W[Kact,N] + bias)
// mma.sync m16n8k16 + ldmatrix (generic PTX). 8 warps, BN=128, BK=32.
// Warp tile: 64 x (BN/warpsN). Double-buffered padded smem.
// ---------------------------------------------------------------------------
template<int BM>
__global__ __launch_bounds__(256, 1)
void mma_gemm_kernel(const float* __restrict__ Aptr, long offA, long wOff,
                     const float* __restrict__ bias,
                     float* Cptr, long offC,
                     int M, int N, int Kact, int Kp, int act)
{
    constexpr int BN = 128, BK = 32, BKP = 40;      // BKP: padded k-stride (bf16)
    constexpr int NT  = (BM == 128) ? 4 : 2;        // n8-tiles per warp
    constexpr int AV  = BM / 32;                    // float4 A loads per thread
    constexpr int ASZ = BM * BKP;                   // bf16 elems per A array
    constexpr int BSZ = BN * BKP;
    constexpr int STG = 2 * ASZ + 2 * BSZ;          // Ah, Al, Bh, Bl

    extern __shared__ __align__(16) __nv_bfloat16 sm[];
    const float* A = Aptr ? Aptr : (const float*)(g_scratch + offA);
    float*       C = Cptr ? Cptr : (g_scratch + offC);
    const __nv_bfloat16* Bwh = g_wbf + wOff;
    const __nv_bfloat16* Bwl = g_wbf + wOff + WTOTAL;

    const int tid  = threadIdx.x;
    const int wid  = tid >> 5, lane = tid & 31;
    const int brow = blockIdx.y * BM, bcol = blockIdx.x * BN;
    const int wm   = (BM == 128) ? ((wid >> 2) * 64) : 0;
    const int wn   = (BM == 128) ? ((wid & 3) * 32)  : (wid * 16);
    const uint32_t sb = smem_u32(sm);

    float4 aReg[AV];
    uint4  bhReg[2], blReg[2];

    auto ldGA = [&](int t) {
#pragma unroll
        for (int l = 0; l < AV; l++) {
            int idx = tid + l * 256;
            int row = idx >> 3, k4 = idx & 7;
            int gk  = t * BK + k4 * 4;
            aReg[l] = (gk < Kact)
                    ? *(const float4*)&A[(size_t)(brow + row) * Kact + gk]
                    : make_float4(0.f, 0.f, 0.f, 0.f);
        }
    };
    auto ldGB = [&](int t) {
#pragma unroll
        for (int l = 0; l < 2; l++) {
            int idx = tid + l * 256;
            int row = idx >> 2, k8 = idx & 3;
            size_t o = (size_t)(bcol + row) * Kp + t * BK + k8 * 8;
            bhReg[l] = *(const uint4*)&Bwh[o];
            blReg[l] = *(const uint4*)&Bwl[o];
        }
    };
    auto stS = [&](int s) {
        __nv_bfloat16* Ah = sm + s * STG;
        __nv_bfloat16* Al = Ah + ASZ;
        __nv_bfloat16* Bh = Al + ASZ;
        __nv_bfloat16* Bl = Bh + BSZ;
#pragma unroll
        for (int l = 0; l < AV; l++) {
            int idx = tid + l * 256;
            int row = idx >> 3, k4 = idx & 7;
            uint2 hp, lp;
            split2(aReg[l].x, aReg[l].y, hp.x, lp.x);
            split2(aReg[l].z, aReg[l].w, hp.y, lp.y);
            *(uint2*)&Ah[row * BKP + k4 * 4] = hp;
            *(uint2*)&Al[row * BKP + k4 * 4] = lp;
        }
#pragma unroll
        for (int l = 0; l < 2; l++) {
            int idx = tid + l * 256;
            int row = idx >> 2, k8 = idx & 3;
            *(uint4*)&Bh[row * BKP + k8 * 8] = bhReg[l];
            *(uint4*)&Bl[row * BKP + k8 * 8] = blReg[l];
        }
    };

    float acc[4][NT][4];
#pragma unroll
    for (int i = 0; i < 4; i++)
#pragma unroll
        for (int j = 0; j < NT; j++)
#pragma unroll
            for (int q = 0; q < 4; q++) acc[i][j][q] = 0.f;

    const int nCh = Kp / BK;
    ldGA(0); ldGB(0);
    stS(0);
    __syncthreads();

    // ldmatrix per-thread offsets (bytes)
    const int aRow = (lane & 7) + ((lane >> 3) & 1) * 8;
    const int aCol = (lane >> 4) * 8;
    const int bRow = (lane & 7) + ((lane >> 4) & 1) * 8;
    const int bCol = ((lane >> 3) & 1) * 8;

    for (int t = 0; t < nCh; t++) {
        if (t + 1 < nCh) { ldGA(t + 1); ldGB(t + 1); }

        const int s = t & 1;
        const uint32_t ahB = sb + (s * STG) * 2;
        const uint32_t alB = ahB + ASZ * 2;
        const uint32_t bhB = alB + ASZ * 2;
        const uint32_t blB = bhB + BSZ * 2;

#pragma unroll
        for (int ks = 0; ks < 2; ks++) {
            uint32_t ah[4][4], al[4][4];
#pragma unroll
            for (int mi = 0; mi < 4; mi++) {
                uint32_t off = ((wm + mi * 16 + aRow) * BKP + ks * 16 + aCol) * 2;
                ldm_x4(ah[mi], ahB + off);
                ldm_x4(al[mi], alB + off);
            }
            uint32_t bh[NT][2], bl[NT][2];
#pragma unroll
            for (int bt = 0; bt < NT / 2; bt++) {
                uint32_t off = ((wn + bt * 16 + bRow) * BKP + ks * 16 + bCol) * 2;
                uint32_t r[4];
                ldm_x4(r, bhB + off);
                bh[2 * bt][0] = r[0]; bh[2 * bt][1] = r[1];
                bh[2 * bt + 1][0] = r[2]; bh[2 * bt + 1][1] = r[3];
                ldm_x4(r, blB + off);
                bl[2 * bt][0] = r[0]; bl[2 * bt][1] = r[1];
                bl[2 * bt + 1][0] = r[2]; bl[2 * bt + 1][1] = r[3];
            }
#pragma unroll
            for (int mi = 0; mi < 4; mi++)
#pragma unroll
                for (int ni = 0; ni < NT; ni++) {
                    mma16816(acc[mi][ni], ah[mi], bh[ni]);
                    mma16816(acc[mi][ni], ah[mi], bl[ni]);
                    mma16816(acc[mi][ni], al[mi], bh[ni]);
                }
        }

        if (t + 1 < nCh) {
            stS((t + 1) & 1);
            __syncthreads();
        }
    }

    // epilogue
#pragma unroll
    for (int mi = 0; mi < 4; mi++) {
#pragma unroll
        for (int ni = 0; ni < NT; ni++) {
            int r0 = brow + wm + mi * 16 + (lane >> 2);
            int c0 = bcol + wn + ni * 8 + 2 * (lane & 3);
#pragma unroll
            for (int half = 0; half < 2; half++) {
                int gr = r0 + half * 8;
                float v0 = acc[mi][ni][2 * half + 0];
                float v1 = acc[mi][ni][2 * half + 1];
                if (c0 < N) {
                    float o = v0 + (bias ? bias[c0] : 0.f);
                    if (act) o = fmaxf(o, 0.f);
                    C[(size_t)gr * N + c0] = o;
                }
                if (c0 + 1 < N) {
                    float o = v1 + (bias ? bias[c0 + 1] : 0.f);
                    if (act) o = fmaxf(o, 0.f);
                    C[(size_t)gr * N + c0 + 1] = o;
                }
            }
        }
    }
}

constexpr int SMEM_128 = (2 * (2 * 128 * 40 + 2 * 128 * 40)) * 2;  // 81920 B
constexpr int SMEM_64  = (2 * (2 * 64 * 40 + 2 * 128 * 40)) * 2;   // 61440 B

static inline void tgemm(const float* A, long offA, long wOff, const float* bias,
                         float* Cp, long offC, int M, int N, int Np,
                         int Kact, int Kp, int act)
{
    if (M >= 4096) {
        dim3 grid(Np / 128, M / 128);
        mma_gemm_kernel<128><<<grid, 256, SMEM_128>>>(A, offA, wOff, bias, Cp, offC,
                                                      M, N, Kact, Kp, act);
    } else {
        dim3 grid(Np / 128, M / 64);
        mma_gemm_kernel<64><<<grid, 256, SMEM_64>>>(A, offA, wOff, bias, Cp, offC,
                                                    M, N, Kact, Kp, act);
    }
}

// ---------------------------------------------------------------------------
// img0[b,k,c] = v_org[b,c,k]
// ---------------------------------------------------------------------------
__global__ void transpose_kernel(const float* __restrict__ v_org)
{
    long idx = (long)blockIdx.x * 256 + threadIdx.x;
    if (idx >= SZ_IMG0) return;
    int  c = (int)(idx % C_);
    long t = idx / C_;
    int  k = (int)(t % K_);
    int  b = (int)(t / K_);
    g_scratch[OFF_IMG0 + idx] = v_org[((long)b * C_ + c) * K_ + k];
}

// ---------------------------------------------------------------------------
// rv gather
// ---------------------------------------------------------------------------
__global__ void gather_rv_kernel(const int* __restrict__ gt_verb,
                                 const int* __restrict__ role_idx,
                                 const float* __restrict__ vt,
                                 const float* __restrict__ rt)
{
    long idx = (long)blockIdx.x * 256 + threadIdx.x;
    if (idx >= SZ_RV) return;
    int e = (int)(idx % TWO_E);
    int n = (int)(idx / TWO_E);
    int b = n / R_;
    float val = (e < E_) ? vt[(long)gt_verb[b] * E_ + e]
                         : rt[(long)role_idx[n] * E_ + (e - E_)];
    g_scratch[OFF_RV + idx] = val;
}

// ---------------------------------------------------------------------------
// Visual attention, one block per batch element b (all R=6 roles together):
// V/img tables read ONCE per b instead of once per (b, role).
// ---------------------------------------------------------------------------
__global__ __launch_bounds__(256) void att6_kernel(
    long offV, long offQA,
    const float* __restrict__ aoW, const float* __restrict__ aoB,
    const float* __restrict__ imgPtr, long offImg, long offOut)
{
    int b  = blockIdx.x;
    int n0 = b * R_;
    const float* V   = g_scratch + offV + (long)b * K_ * H_;
    const float* img = imgPtr ? (imgPtr + (long)b * K_ * C_)
                              : (g_scratch + offImg + (long)b * K_ * C_);

    __shared__ float qa[R_][H_];
    __shared__ float attw[R_][K_ + 1];

    int tid = threadIdx.x, wid = tid >> 5, lane = tid & 31;

    for (int idx = tid; idx < R_ * H_; idx += 256) {
        int r = idx / H_, h = idx % H_;
        qa[r][h] = g_scratch[offQA + (long)(n0 + r) * H_ + h] * aoW[h];
    }
    __syncthreads();

    // logits: warp per k, 6 dots sharing one V-row pass
    for (int k = wid; k < K_; k += 8) {
        const float* vk = V + (long)k * H_;
        float s0=0,s1=0,s2=0,s3=0,s4=0,s5=0;
        for (int h = lane; h < H_; h += 32) {
            float v = vk[h];
            s0 = fmaf(v, qa[0][h], s0); s1 = fmaf(v, qa[1][h], s1);
            s2 = fmaf(v, qa[2][h], s2); s3 = fmaf(v, qa[3][h], s3);
            s4 = fmaf(v, qa[4][h], s4); s5 = fmaf(v, qa[5][h], s5);
        }
#pragma unroll
        for (int o = 16; o; o >>= 1) {
            s0 += __shfl_xor_sync(0xffffffffu, s0, o);
            s1 += __shfl_xor_sync(0xffffffffu, s1, o);
            s2 += __shfl_xor_sync(0xffffffffu, s2, o);
            s3 += __shfl_xor_sync(0xffffffffu, s3, o);
            s4 += __shfl_xor_sync(0xffffffffu, s4, o);
            s5 += __shfl_xor_sync(0xffffffffu, s5, o);
        }
        if (lane == 0) {
            float ab = aoB[0];
            attw[0][k] = s0 + ab; attw[1][k] = s1 + ab; attw[2][k] = s2 + ab;
            attw[3][k] = s3 + ab; attw[4][k] = s4 + ab; attw[5][k] = s5 + ab;
        }
    }
    __syncthreads();

    // softmax over k per role (6 threads)
    if (tid < R_) {
        float mx = -1e30f;
        for (int k = 0; k < K_; k++) mx = fmaxf(mx, attw[tid][k]);
        float sum = 0.f;
        for (int k = 0; k < K_; k++) sum += expf(attw[tid][k] - mx);
        float inv = 1.f / sum;
        for (int k = 0; k < K_; k++) attw[tid][k] = expf(attw[tid][k] - mx) * inv;
    }
    __syncthreads();

    // vemb: img row pass shared by 6 roles
    for (int c = tid; c < C_; c += 256) {
        float a0=0,a1=0,a2=0,a3=0,a4=0,a5=0;
#pragma unroll 7
        for (int k = 0; k < K_; k++) {
            float f = img[(long)k * C_ + c];
            a0 = fmaf(attw[0][k], f, a0); a1 = fmaf(attw[1][k], f, a1);
            a2 = fmaf(attw[2][k], f, a2); a3 = fmaf(attw[3][k], f, a3);
            a4 = fmaf(attw[4][k], f, a4); a5 = fmaf(attw[5][k], f, a5);
        }
        float* out = g_scratch + offOut + (long)n0 * C_ + c;
        out[0]      = a0; out[C_]     = a1; out[2*C_] = a2;
        out[3*C_]   = a3; out[4*C_]   = a4; out[5*C_] = a5;
    }
}

// ---------------------------------------------------------------------------
// MFB pool
// ---------------------------------------------------------------------------
__global__ void mfb_kernel(long offQ, long offV, long offOut)
{
    int n = blockIdx.x;
    const float* q = g_scratch + offQ   + (long)n * H_;
    const float* v = g_scratch + offV   + (long)n * H_;
    float*       o = g_scratch + offOut + (long)n * H_;
    int tid = threadIdx.x;

    float s = 0.f;
    for (int h = tid; h < H_; h += 256) {
        float z = q[h] * v[h];
        s += fabsf(z);
    }
    __shared__ float red[8];
#pragma unroll
    for (int off = 16; off; off >>= 1) s += __shfl_xor_sync(0xffffffffu, s, off);
    if ((tid & 31) == 0) red[tid >> 5] = s;
    __syncthreads();
    float tot = 0.f;
#pragma unroll
    for (int i = 0; i < 8; i++) tot += red[i];
    float inv = 1.f / fmaxf(sqrtf(tot), 1e-12f);

    for (int h = tid; h < H_; h += 256) {
        float z = q[h] * v[h];
        float sg = (z > 0.f) ? sqrtf(z) : -sqrtf(-z);
        o[h] = sg * inv;
    }
}

// ---------------------------------------------------------------------------
// Masked role attention (single head), one block per batch element
// ---------------------------------------------------------------------------
__global__ void role_att_kernel(const int* __restrict__ mask)
{
    int b = blockIdx.x;
    const float* qh = g_scratch + OFF_QH + (long)b * R_ * H_;
    const float* kh = g_scratch + OFF_KH + (long)b * R_ * H_;
    const float* vh = g_scratch + OFF_VH + (long)b * R_ * H_;
    float*      ctx = g_scratch + OFF_CTX + (long)b * R_ * H_;

    __shared__ float sc[R_][R_];
    __shared__ float attn[R_][R_];
    int tid = threadIdx.x, wid = tid >> 5, lane = tid & 31;

    for (int p = wid; p < R_ * R_; p += 8) {
        int i = p / R_, j = p % R_;
        float s = 0.f;
        for (int h = lane; h < H_; h += 32)
            s = fmaf(qh[i * H_ + h], kh[j * H_ + h], s);
#pragma unroll
        for (int o = 16; o; o >>= 1) s += __shfl_xor_sync(0xffffffffu, s, o);
        if (lane == 0) {
            bool valid = (i != j) && (mask[((long)b * R_ + i) * R_ + j] > 0);
            sc[i][j] = valid ? s * (1.f / 32.f) : -1e9f;
        }
    }
    __syncthreads();

    if (tid < R_ * R_) {
        int i = tid / R_, j = tid % R_;
        float mx = -1e30f;
        for (int jj = 0; jj < R_; jj++) mx = fmaxf(mx, sc[i][jj]);
        float sum = 0.f;
        for (int jj = 0; jj < R_; jj++) sum += expf(sc[i][jj] - mx);
        attn[i][j] = expf(sc[i][j] - mx) / sum;
    }
    __syncthreads();

    for (int idx = tid; idx < R_ * H_; idx += 256) {
        int i = idx / H_, h = idx % H_;
        float acc = 0.f;
#pragma unroll
        for (int j = 0; j < R_; j++)
            acc = fmaf(attn[i][j], vh[j * H_ + h], acc);
        ctx[idx] = acc;
    }
}

// ---------------------------------------------------------------------------
// cat = [neigh | rv]
// ---------------------------------------------------------------------------
__global__ void concat_kernel()
{
    long idx = (long)blockIdx.x * 256 + threadIdx.x;
    if (idx >= SZ_CAT) return;
    int col = (int)(idx % CATW);
    int n   = (int)(idx / CATW);
    float v = (col < H_) ? g_scratch[OFF_NEIGH + (long)n * H_ + col]
                         : g_scratch[OFF_RV + (long)n * TWO_E + (col - H_)];
    g_scratch[OFF_CAT + idx] = v;
}

// ---------------------------------------------------------------------------
// gated fusion
// ---------------------------------------------------------------------------
__global__ void combine_kernel()
{
    long idx = (long)blockIdx.x * 256 + threadIdx.x;
    if (idx >= SZ_H) return;
    float o2 = g_scratch[OFF_OUT2 + idx];
    float ov = g_scratch[OFF_OUTV + idx];
    float a0 = g_scratch[OFF_OUT + idx];
    float g  = 1.f / (1.f + expf(-(o2 + ov)));
    g_scratch[OFF_OUTF + idx] = (1.f - g) * ov + g * tanhf(o2 + a0);
}

// ---------------------------------------------------------------------------
// Launch sequence
// ---------------------------------------------------------------------------
extern "C" void kernel_launch(void* const* d_in, const int* in_sizes, int n_in,
                              void* d_out, int out_size)
{
    const float* v_org    = (const float*)d_in[0];
    const float* img_feat = (const float*)d_in[1];
    const int*   gt_verb  = (const int*)d_in[2];
    const int*   role_idx = (const int*)d_in[3];
    const int*   mask     = (const int*)d_in[4];
    const float* verb_t   = (const float*)d_in[5];
    const float* role_t   = (const float*)d_in[6];
    const float* qc_W = (const float*)d_in[7];   const float* qc_b = (const float*)d_in[8];
    const float* av_W = (const float*)d_in[9];   const float* av_b = (const float*)d_in[10];
    const float* aq_W = (const float*)d_in[11];  const float* aq_b = (const float*)d_in[12];
    const float* ao_W = (const float*)d_in[13];  const float* ao_b = (const float*)d_in[14];
    const float* vn_W = (const float*)d_in[15];  const float* vn_b = (const float*)d_in[16];
    const float* qn_W = (const float*)d_in[17];  const float* qn_b = (const float*)d_in[18];
    const float* Wq   = (const float*)d_in[19];
    const float* Wk   = (const float*)d_in[20];
    const float* Wv   = (const float*)d_in[21];
    const float* Wo   = (const float*)d_in[22];
    const float* uqc_W = (const float*)d_in[23]; const float* uqc_b = (const float*)d_in[24];
    const float* cls_W = (const float*)d_in[25]; const float* cls_b = (const float*)d_in[26];

    cudaFuncSetAttribute(mma_gemm_kernel<128>,
                         cudaFuncAttributeMaxDynamicSharedMemorySize, SMEM_128);
    cudaFuncSetAttribute(mma_gemm_kernel<64>,
                         cudaFuncAttributeMaxDynamicSharedMemorySize, SMEM_64);

    // prep
    transpose_kernel<<<(int)((SZ_IMG0 + 255) / 256), 256>>>(v_org);
    gather_rv_kernel<<<(int)((SZ_RV + 255) / 256), 256>>>(gt_verb, role_idx, verb_t, role_t);

    // weight transpose + bf16 split
    auto wc = [&](const float* W, int K, int N, int Kp, int Np, long off) {
        dim3 g(Kp / 32, Np / 32);
        wconv_kernel<<<g, dim3(32, 8)>>>(W, K, N, Kp, Np, off);
    };
    wc(qc_W,  600, 1024,  640, 1024, WOFF_QC);
    wc(av_W,  512, 1024,  512, 1024, WOFF_AV);
    wc(aq_W, 1024, 1024, 1024, 1024, WOFF_AQ);
    wc(qn_W, 1024, 1024, 1024, 1024, WOFF_QN);
    wc(vn_W,  512, 1024,  512, 1024, WOFF_VN);
    wc(Wq,   1024, 1024, 1024, 1024, WOFF_WQ);
    wc(Wk,   1024, 1024, 1024, 1024, WOFF_WK);
    wc(Wv,   1024, 1024, 1024, 1024, WOFF_WV);
    wc(Wo,   1024, 1024, 1024, 1024, WOFF_WO);
    wc(uqc_W, CATW, 1024, 1664, 1024, WOFF_UQC);
    wc(cls_W, 1024, NL_, 1024, 2048, WOFF_CLS);

    // image value projections (computed ONCE, reused by all 3 attention calls)
    tgemm(nullptr, OFF_IMG0, WOFF_AV, av_b, nullptr, OFF_V1, B_ * K_, 1024, 1024, 512, 512, 1);
    tgemm(img_feat, 0,       WOFF_AV, av_b, nullptr, OFF_V2, B_ * K_, 1024, 1024, 512, 512, 1);

    // query chain
    tgemm(nullptr, OFF_RV,   WOFF_QC, qc_b, nullptr, OFF_QEMB,  BR_, 1024, 1024, 600, 640, 1);
    tgemm(nullptr, OFF_QEMB, WOFF_AQ, aq_b, nullptr, OFF_QA,    BR_, 1024, 1024, 1024, 1024, 1);
    tgemm(nullptr, OFF_QEMB, WOFF_QN, qn_b, nullptr, OFF_QREPR, BR_, 1024, 1024, 1024, 1024, 1);

    // attention 1 (spatial image) and attention-verb (img_feat)
    att6_kernel<<<B_, 256>>>(OFF_V1, OFF_QA, ao_W, ao_b, nullptr,  OFF_IMG0, OFF_VEMB1);
    att6_kernel<<<B_, 256>>>(OFF_V2, OFF_QA, ao_W, ao_b, img_feat, 0,        OFF_VEMB2);

    tgemm(nullptr, OFF_VEMB1, WOFF_VN, vn_b, nullptr, OFF_VREPR1, BR_, 1024, 1024, 512, 512, 1);
    tgemm(nullptr, OFF_VEMB2, WOFF_VN, vn_b, nullptr, OFF_VREPRV, BR_, 1024, 1024, 512, 512, 1);

    mfb_kernel<<<BR_, 256>>>(OFF_QREPR, OFF_VREPR1, OFF_OUT);
    mfb_kernel<<<BR_, 256>>>(OFF_QREPR, OFF_VREPRV, OFF_OUTV);

    // role-node neighbour attention
    tgemm(nullptr, OFF_OUT, WOFF_WQ, nullptr, nullptr, OFF_QH, BR_, 1024, 1024, 1024, 1024, 0);
    tgemm(nullptr, OFF_OUT, WOFF_WK, nullptr, nullptr, OFF_KH, BR_, 1024, 1024, 1024, 1024, 0);
    tgemm(nullptr, OFF_OUT, WOFF_WV, nullptr, nullptr, OFF_VH, BR_, 1024, 1024, 1024, 1024, 0);
    role_att_kernel<<<B_, 256>>>(mask);
    tgemm(nullptr, OFF_CTX, WOFF_WO, nullptr, nullptr, OFF_NEIGH, BR_, 1024, 1024, 1024, 1024, 0);

    // updated query
    concat_kernel<<<(int)((SZ_CAT + 255) / 256), 256>>>();
    tgemm(nullptr, OFF_CAT, WOFF_UQC, uqc_b, nullptr, OFF_UQ,     BR_, 1024, 1024, CATW, 1664, 1);
    tgemm(nullptr, OFF_UQ,  WOFF_AQ,  aq_b,  nullptr, OFF_QA2,    BR_, 1024, 1024, 1024, 1024, 1);
    tgemm(nullptr, OFF_UQ,  WOFF_QN,  qn_b,  nullptr, OFF_QREPR2, BR_, 1024, 1024, 1024, 1024, 1);

    // attention 2 on spatial image with updated query
    att6_kernel<<<B_, 256>>>(OFF_V1, OFF_QA2, ao_W, ao_b, nullptr, OFF_IMG0, OFF_VEMB3);
    tgemm(nullptr, OFF_VEMB3, WOFF_VN, vn_b, nullptr, OFF_VREPR2, BR_, 1024, 1024, 512, 512, 1);
    mfb_kernel<<<BR_, 256>>>(OFF_QREPR2, OFF_VREPR2, OFF_OUT2);

    // gated fusion
    combine_kernel<<<(int)((SZ_H + 255) / 256), 256>>>();

    // classifier -> d_out
    tgemm(nullptr, OFF_OUTF, WOFF_CLS, cls_b, (float*)d_out, 0, BR_, NL_, 2048, 1024, 1024, 0);
}

// round 5
// speedup vs baseline: 3.1796x; 1.2262x over previous
#include <cuda_runtime.h>
#include <cuda_bf16.h>
#include <cstdint>
#include <math.h>

// ---------------------------------------------------------------------------
// Problem dims
// ---------------------------------------------------------------------------
constexpr int B_   = 256;
constexpr int R_   = 6;
constexpr int K_   = 49;
constexpr int C_   = 512;
constexpr int H_   = 1024;
constexpr int E_   = 300;
constexpr int BR_  = B_ * R_;          // 1536
constexpr int NL_  = 2001;
constexpr int TWO_E = 2 * E_;          // 600
constexpr int CATW  = H_ + TWO_E;      // 1624

// ---------------------------------------------------------------------------
// fp32 scratch
// ---------------------------------------------------------------------------
constexpr long SZ_IMG0 = (long)B_ * K_ * C_;
constexpr long SZ_V    = (long)B_ * K_ * H_;
constexpr long SZ_RV   = (long)BR_ * TWO_E;
constexpr long SZ_H    = (long)BR_ * H_;
constexpr long SZ_2H   = (long)BR_ * 2048;
constexpr long SZ_3H   = (long)BR_ * 3072;
constexpr long SZ_C    = (long)BR_ * C_;
constexpr long SZ_CAT  = (long)BR_ * CATW;

constexpr long OFF_IMG0  = 0;
constexpr long OFF_V1    = OFF_IMG0  + SZ_IMG0;
constexpr long OFF_V2    = OFF_V1    + SZ_V;
constexpr long OFF_RV    = OFF_V2    + SZ_V;
constexpr long OFF_QEMB  = OFF_RV    + SZ_RV;
constexpr long OFF_QAQR  = OFF_QEMB  + SZ_H;    // [BR, 2048] = [qa | qrepr]
constexpr long OFF_VEMB1 = OFF_QAQR  + SZ_2H;   // [BR,512]
constexpr long OFF_VEMB2 = OFF_VEMB1 + SZ_C;    // [BR,512] (contiguous after VEMB1)
constexpr long OFF_VREPR1= OFF_VEMB2 + SZ_C;    // [BR,1024]
constexpr long OFF_VREPRV= OFF_VREPR1+ SZ_H;    // contiguous
constexpr long OFF_OUT   = OFF_VREPRV+ SZ_H;
constexpr long OFF_OUTV  = OFF_OUT   + SZ_H;    // contiguous after OUT
constexpr long OFF_QKV3  = OFF_OUTV  + SZ_H;    // [BR, 3072] = [q|k|v]
constexpr long OFF_CTX   = OFF_QKV3  + SZ_3H;
constexpr long OFF_NEIGH = OFF_CTX   + SZ_H;
constexpr long OFF_CAT   = OFF_NEIGH + SZ_H;
constexpr long OFF_UQ    = OFF_CAT   + SZ_CAT;
constexpr long OFF_QAQR2 = OFF_UQ    + SZ_H;    // [BR, 2048]
constexpr long OFF_VEMB3 = OFF_QAQR2 + SZ_2H;
constexpr long OFF_VREPR2= OFF_VEMB3 + SZ_C;
constexpr long OFF_OUT2  = OFF_VREPR2+ SZ_H;
constexpr long OFF_OUTF  = OFF_OUT2  + SZ_H;
constexpr long OFF_BIASAQN = OFF_OUTF + SZ_H;   // 2048 floats [aq_b|qn_b]
constexpr long SCRATCH_TOTAL = OFF_BIASAQN + 2048;

__device__ float g_scratch[SCRATCH_TOTAL];

// ---------------------------------------------------------------------------
// bf16 weight buffers (transposed [Npad][Kpad], hi at off, lo at off+WTOTAL)
// ---------------------------------------------------------------------------
constexpr long WOFF_QC  = 0;                           // [1024][640]
constexpr long WOFF_AV  = WOFF_QC  + 1024L * 640;      // [1024][512]
constexpr long WOFF_AQN = WOFF_AV  + 1024L * 512;      // [2048][1024] = [aq ; qn]
constexpr long WOFF_VN  = WOFF_AQN + 2048L * 1024;     // [1024][512]
constexpr long WOFF_QKV = WOFF_VN  + 1024L * 512;      // [3072][1024] = [Wq;Wk;Wv]
constexpr long WOFF_WO  = WOFF_QKV + 3072L * 1024;     // [1024][1024]
constexpr long WOFF_UQC = WOFF_WO  + 1024L * 1024;     // [1024][1664]
constexpr long WOFF_CLS = WOFF_UQC + 1024L * 1664;     // [2048][1024]
constexpr long WTOTAL   = WOFF_CLS + 2048L * 1024;

__device__ __nv_bfloat16 g_wbf[2 * WTOTAL];

// ---------------------------------------------------------------------------
// helpers
// ---------------------------------------------------------------------------
__device__ __forceinline__ uint32_t smem_u32(const void* p) {
    uint32_t a;
    asm("{ .reg .u64 t; cvta.to.shared.u64 t, %1; cvt.u32.u64 %0, t; }" : "=r"(a) : "l"(p));
    return a;
}
__device__ __forceinline__ void split2(float x, float y, uint32_t& hp, uint32_t& lp) {
    __nv_bfloat16 hx = __float2bfloat16(x), hy = __float2bfloat16(y);
    __nv_bfloat16 lx = __float2bfloat16(x - __bfloat162float(hx));
    __nv_bfloat16 ly = __float2bfloat16(y - __bfloat162float(hy));
    hp = (uint32_t)__bfloat16_as_ushort(hx) | ((uint32_t)__bfloat16_as_ushort(hy) << 16);
    lp = (uint32_t)__bfloat16_as_ushort(lx) | ((uint32_t)__bfloat16_as_ushort(ly) << 16);
}
__device__ __forceinline__ void ldm_x4(uint32_t* r, uint32_t addr) {
    asm volatile("ldmatrix.sync.aligned.m8n8.x4.shared.b16 {%0,%1,%2,%3}, [%4];"
                 : "=r"(r[0]), "=r"(r[1]), "=r"(r[2]), "=r"(r[3]) : "r"(addr));
}
__device__ __forceinline__ void mma16816(float* c, const uint32_t* a, const uint32_t* b) {
    asm volatile(
        "mma.sync.aligned.m16n8k16.row.col.f32.bf16.bf16.f32 "
        "{%0,%1,%2,%3}, {%4,%5,%6,%7}, {%8,%9}, {%0,%1,%2,%3};"
        : "+f"(c[0]), "+f"(c[1]), "+f"(c[2]), "+f"(c[3])
        : "r"(a[0]), "r"(a[1]), "r"(a[2]), "r"(a[3]), "r"(b[0]), "r"(b[1]));
}
__device__ __forceinline__ void cpa16(uint32_t s, const void* g) {
    asm volatile("cp.async.cg.shared.global [%0], [%1], 16;" :: "r"(s), "l"(g));
}
#define CP_COMMIT() asm volatile("cp.async.commit_group;" ::: "memory")
#define CP_WAIT0()  asm volatile("cp.async.wait_group 0;" ::: "memory")

// ---------------------------------------------------------------------------
// Weight transpose + bf16 hi/lo split:  W[K,N] fp32 -> g_wbf [Npad][Kpad]
// ---------------------------------------------------------------------------
__global__ void wconv_kernel(const float* __restrict__ W,
                             int K, int N, int Kp, int Np, long off)
{
    __shared__ float tile[32][33];
    int k0 = blockIdx.x * 32, n0 = blockIdx.y * 32;
    int tx = threadIdx.x, ty = threadIdx.y;
#pragma unroll
    for (int i = 0; i < 32; i += 8) {
        int k = k0 + ty + i, n = n0 + tx;
        tile[ty + i][tx] = (k < K && n < N) ? W[(size_t)k * N + n] : 0.f;
    }
    __syncthreads();
#pragma unroll
    for (int i = 0; i < 32; i += 8) {
        int n = n0 + ty + i, k = k0 + tx;
        float v = tile[tx][ty + i];
        __nv_bfloat16 h = __float2bfloat16(v);
        __nv_bfloat16 l = __float2bfloat16(v - __bfloat162float(h));
        long o = off + (long)n * Kp + k;
        g_wbf[o] = h;
        g_wbf[o + WTOTAL] = l;
    }
}

// pack [aq_b | qn_b] -> scratch
__global__ void packb_kernel(const float* __restrict__ b0, const float* __restrict__ b1)
{
    int i = blockIdx.x * 256 + threadIdx.x;
    if (i < 1024) g_scratch[OFF_BIASAQN + i] = b0[i];
    else if (i < 2048) g_scratch[OFF_BIASAQN + i] = b1[i - 1024];
}

// ---------------------------------------------------------------------------
// HMMA bf16-split GEMM: C[M,N] = act(A[M,Kact] @ W[Kact,N] + bias)
// mma.sync m16n8k16 + ldmatrix. 8 warps (2x4), BN=128, BK=32.
// B via cp.async; A converted in-register. Double-buffered padded smem.
// ---------------------------------------------------------------------------
template<int BM>
__global__ __launch_bounds__(256)
void mma_gemm_kernel(const float* __restrict__ Aptr, long offA, long wOff,
                     const float* __restrict__ biasPtr, long biasOff,
                     float* Cptr, long offC,
                     int M, int N, int Kact, int Kp, int act)
{
    constexpr int BN = 128, BK = 32, BKP = 40;
    constexpr int MI  = BM / 32;            // 16-row m-tiles per warp
    constexpr int NT  = 4;                  // n8-tiles per warp
    constexpr int AV  = BM / 32;            // float4 A loads per thread
    constexpr int ASZ = BM * BKP;           // bf16 elems
    constexpr int BSZ = BN * BKP;
    constexpr int STG = 2 * ASZ + 2 * BSZ;  // Ah, Al, Bh, Bl

    extern __shared__ __align__(16) __nv_bfloat16 sm[];
    const float* A = Aptr ? Aptr : (const float*)(g_scratch + offA);
    float*       C = Cptr ? Cptr : (g_scratch + offC);
    const float* bias = biasPtr ? biasPtr
                      : (biasOff >= 0 ? (const float*)(g_scratch + biasOff) : nullptr);
    const __nv_bfloat16* Bwh = g_wbf + wOff;
    const __nv_bfloat16* Bwl = g_wbf + wOff + WTOTAL;

    const int tid  = threadIdx.x;
    const int wid  = tid >> 5, lane = tid & 31;
    const int brow = blockIdx.y * BM, bcol = blockIdx.x * BN;
    const int wm   = (wid >> 2) * (BM / 2);
    const int wn   = (wid & 3) * 32;
    const uint32_t sb = smem_u32(sm);

    float4 aReg[AV];

    auto ldGA = [&](int t) {
#pragma unroll
        for (int l = 0; l < AV; l++) {
            int idx = tid + l * 256;
            int row = idx >> 3, k4 = idx & 7;
            int gk  = t * BK + k4 * 4;
            aReg[l] = (gk < Kact)
                    ? *(const float4*)&A[(size_t)(brow + row) * Kact + gk]
                    : make_float4(0.f, 0.f, 0.f, 0.f);
        }
    };
    auto stA = [&](int s) {
        __nv_bfloat16* Ah = sm + s * STG;
        __nv_bfloat16* Al = Ah + ASZ;
#pragma unroll
        for (int l = 0; l < AV; l++) {
            int idx = tid + l * 256;
            int row = idx >> 3, k4 = idx & 7;
            uint2 hp, lp;
            split2(aReg[l].x, aReg[l].y, hp.x, lp.x);
            split2(aReg[l].z, aReg[l].w, hp.y, lp.y);
            *(uint2*)&Ah[row * BKP + k4 * 4] = hp;
            *(uint2*)&Al[row * BKP + k4 * 4] = lp;
        }
    };
    auto cpB = [&](int t, int s) {
        uint32_t bh = sb + (uint32_t)(s * STG + 2 * ASZ) * 2;
        uint32_t bl = bh + (uint32_t)BSZ * 2;
#pragma unroll
        for (int l = 0; l < 2; l++) {
            int idx = tid + l * 256;          // 0..511
            int row = idx >> 2, seg = idx & 3;
            size_t go = (size_t)(bcol + row) * Kp + t * BK + seg * 8;
            uint32_t so = (uint32_t)(row * BKP + seg * 8) * 2;
            cpa16(bh + so, Bwh + go);
            cpa16(bl + so, Bwl + go);
        }
    };

    float acc[MI][NT][4];
#pragma unroll
    for (int i = 0; i < MI; i++)
#pragma unroll
        for (int j = 0; j < NT; j++)
#pragma unroll
            for (int q = 0; q < 4; q++) acc[i][j][q] = 0.f;

    const int nCh = Kp / BK;

    cpB(0, 0); CP_COMMIT();
    ldGA(0);   stA(0);
    CP_WAIT0();
    __syncthreads();

    const int aRow = (lane & 7) + ((lane >> 3) & 1) * 8;
    const int aCol = (lane >> 4) * 8;
    const int bRow = (lane & 7) + ((lane >> 4) & 1) * 8;
    const int bCol = ((lane >> 3) & 1) * 8;

    for (int t = 0; t < nCh; t++) {
        const int s = t & 1;
        if (t + 1 < nCh) {
            ldGA(t + 1);
            cpB(t + 1, s ^ 1);
            CP_COMMIT();
        }

        const uint32_t ahB = sb + (uint32_t)(s * STG) * 2;
        const uint32_t alB = ahB + (uint32_t)ASZ * 2;
        const uint32_t bhB = alB + (uint32_t)ASZ * 2;
        const uint32_t blB = bhB + (uint32_t)BSZ * 2;

#pragma unroll
        for (int ks = 0; ks < 2; ks++) {
            uint32_t ah[MI][4], al[MI][4];
#pragma unroll
            for (int mi = 0; mi < MI; mi++) {
                uint32_t off = (uint32_t)((wm + mi * 16 + aRow) * BKP + ks * 16 + aCol) * 2;
                ldm_x4(ah[mi], ahB + off);
                ldm_x4(al[mi], alB + off);
            }
            uint32_t bh[NT][2], bl[NT][2];
#pragma unroll
            for (int bt = 0; bt < NT / 2; bt++) {
                uint32_t off = (uint32_t)((wn + bt * 16 + bRow) * BKP + ks * 16 + bCol) * 2;
                uint32_t r[4];
                ldm_x4(r, bhB + off);
                bh[2 * bt][0] = r[0]; bh[2 * bt][1] = r[1];
                bh[2 * bt + 1][0] = r[2]; bh[2 * bt + 1][1] = r[3];
                ldm_x4(r, blB + off);
                bl[2 * bt][0] = r[0]; bl[2 * bt][1] = r[1];
                bl[2 * bt + 1][0] = r[2]; bl[2 * bt + 1][1] = r[3];
            }
#pragma unroll
            for (int mi = 0; mi < MI; mi++)
#pragma unroll
                for (int ni = 0; ni < NT; ni++) {
                    mma16816(acc[mi][ni], ah[mi], bh[ni]);
                    mma16816(acc[mi][ni], ah[mi], bl[ni]);
                    mma16816(acc[mi][ni], al[mi], bh[ni]);
                }
        }

        if (t + 1 < nCh) {
            stA(s ^ 1);
            CP_WAIT0();
            __syncthreads();
        }
    }

    // epilogue
#pragma unroll
    for (int mi = 0; mi < MI; mi++) {
#pragma unroll
        for (int ni = 0; ni < NT; ni++) {
            int r0 = brow + wm + mi * 16 + (lane >> 2);
            int c0 = bcol + wn + ni * 8 + 2 * (lane & 3);
#pragma unroll
            for (int half = 0; half < 2; half++) {
                int gr = r0 + half * 8;
                float v0 = acc[mi][ni][2 * half + 0];
                float v1 = acc[mi][ni][2 * half + 1];
                if (c0 < N) {
                    float o = v0 + (bias ? bias[c0] : 0.f);
                    if (act) o = fmaxf(o, 0.f);
                    C[(size_t)gr * N + c0] = o;
                }
                if (c0 + 1 < N) {
                    float o = v1 + (bias ? bias[c0 + 1] : 0.f);
                    if (act) o = fmaxf(o, 0.f);
                    C[(size_t)gr * N + c0 + 1] = o;
                }
            }
        }
    }
}

constexpr int SMEM_128 = (2 * (2 * 128 * 40 + 2 * 128 * 40)) * 2;  // 81920 B
constexpr int SMEM_64  = (2 * (2 * 64 * 40 + 2 * 128 * 40)) * 2;   // 61440 B

static inline void tgemm(const float* A, long offA, long wOff,
                         const float* bias, long biasOff,
                         float* Cp, long offC, int M, int N, int Np,
                         int Kact, int Kp, int act)
{
    if (M >= 4096) {
        dim3 grid(Np / 128, M / 128);
        mma_gemm_kernel<128><<<grid, 256, SMEM_128>>>(A, offA, wOff, bias, biasOff,
                                                      Cp, offC, M, N, Kact, Kp, act);
    } else {
        dim3 grid(Np / 128, M / 64);
        mma_gemm_kernel<64><<<grid, 256, SMEM_64>>>(A, offA, wOff, bias, biasOff,
                                                    Cp, offC, M, N, Kact, Kp, act);
    }
}

// ---------------------------------------------------------------------------
// img0[b,k,c] = v_org[b,c,k]
// ---------------------------------------------------------------------------
__global__ void transpose_kernel(const float* __restrict__ v_org)
{
    long idx = (long)blockIdx.x * 256 + threadIdx.x;
    if (idx >= SZ_IMG0) return;
    int  c = (int)(idx % C_);
    long t = idx / C_;
    int  k = (int)(t % K_);
    int  b = (int)(t / K_);
    g_scratch[OFF_IMG0 + idx] = v_org[((long)b * C_ + c) * K_ + k];
}

// ---------------------------------------------------------------------------
// rv gather
// ---------------------------------------------------------------------------
__global__ void gather_rv_kernel(const int* __restrict__ gt_verb,
                                 const int* __restrict__ role_idx,
                                 const float* __restrict__ vt,
                                 const float* __restrict__ rt)
{
    long idx = (long)blockIdx.x * 256 + threadIdx.x;
    if (idx >= SZ_RV) return;
    int e = (int)(idx % TWO_E);
    int n = (int)(idx / TWO_E);
    int b = n / R_;
    float val = (e < E_) ? vt[(long)gt_verb[b] * E_ + e]
                         : rt[(long)role_idx[n] * E_ + (e - E_)];
    g_scratch[OFF_RV + idx] = val;
}

// ---------------------------------------------------------------------------
// Visual attention, one block per batch element (all R=6 roles):
// qa row n read from g_scratch[offQA + n*qStride + h]
// ---------------------------------------------------------------------------
__global__ __launch_bounds__(256) void att6_kernel(
    long offV, long offQA, int qStride,
    const float* __restrict__ aoW, const float* __restrict__ aoB,
    const float* __restrict__ imgPtr, long offImg, long offOut)
{
    int b  = blockIdx.x;
    int n0 = b * R_;
    const float* V   = g_scratch + offV + (long)b * K_ * H_;
    const float* img = imgPtr ? (imgPtr + (long)b * K_ * C_)
                              : (g_scratch + offImg + (long)b * K_ * C_);

    __shared__ float qa[R_][H_];
    __shared__ float attw[R_][K_ + 1];

    int tid = threadIdx.x, wid = tid >> 5, lane = tid & 31;

    for (int idx = tid; idx < R_ * H_; idx += 256) {
        int r = idx / H_, h = idx % H_;
        qa[r][h] = g_scratch[offQA + (long)(n0 + r) * qStride + h] * aoW[h];
    }
    __syncthreads();

    for (int k = wid; k < K_; k += 8) {
        const float* vk = V + (long)k * H_;
        float s0=0,s1=0,s2=0,s3=0,s4=0,s5=0;
        for (int h = lane; h < H_; h += 32) {
            float v = vk[h];
            s0 = fmaf(v, qa[0][h], s0); s1 = fmaf(v, qa[1][h], s1);
            s2 = fmaf(v, qa[2][h], s2); s3 = fmaf(v, qa[3][h], s3);
            s4 = fmaf(v, qa[4][h], s4); s5 = fmaf(v, qa[5][h], s5);
        }
#pragma unroll
        for (int o = 16; o; o >>= 1) {
            s0 += __shfl_xor_sync(0xffffffffu, s0, o);
            s1 += __shfl_xor_sync(0xffffffffu, s1, o);
            s2 += __shfl_xor_sync(0xffffffffu, s2, o);
            s3 += __shfl_xor_sync(0xffffffffu, s3, o);
            s4 += __shfl_xor_sync(0xffffffffu, s4, o);
            s5 += __shfl_xor_sync(0xffffffffu, s5, o);
        }
        if (lane == 0) {
            float ab = aoB[0];
            attw[0][k] = s0 + ab; attw[1][k] = s1 + ab; attw[2][k] = s2 + ab;
            attw[3][k] = s3 + ab; attw[4][k] = s4 + ab; attw[5][k] = s5 + ab;
        }
    }
    __syncthreads();

    if (tid < R_) {
        float mx = -1e30f;
        for (int k = 0; k < K_; k++) mx = fmaxf(mx, attw[tid][k]);
        float sum = 0.f;
        for (int k = 0; k < K_; k++) sum += expf(attw[tid][k] - mx);
        float inv = 1.f / sum;
        for (int k = 0; k < K_; k++) attw[tid][k] = expf(attw[tid][k] - mx) * inv;
    }
    __syncthreads();

    for (int c = tid; c < C_; c += 256) {
        float a0=0,a1=0,a2=0,a3=0,a4=0,a5=0;
#pragma unroll 7
        for (int k = 0; k < K_; k++) {
            float f = img[(long)k * C_ + c];
            a0 = fmaf(attw[0][k], f, a0); a1 = fmaf(attw[1][k], f, a1);
            a2 = fmaf(attw[2][k], f, a2); a3 = fmaf(attw[3][k], f, a3);
            a4 = fmaf(attw[4][k], f, a4); a5 = fmaf(attw[5][k], f, a5);
        }
        float* out = g_scratch + offOut + (long)n0 * C_ + c;
        out[0]      = a0; out[C_]     = a1; out[2*C_] = a2;
        out[3*C_]   = a3; out[4*C_]   = a4; out[5*C_] = a5;
    }
}

// ---------------------------------------------------------------------------
// MFB pool: q row = offQ + (n % qWrap)*qStride; v/o rows linear in n
// ---------------------------------------------------------------------------
__global__ void mfb_kernel(long offQ, int qStride, int qWrap,
                           long offV, long offOut)
{
    int n = blockIdx.x;
    const float* q = g_scratch + offQ   + (long)(n % qWrap) * qStride;
    const float* v = g_scratch + offV   + (long)n * H_;
    float*       o = g_scratch + offOut + (long)n * H_;
    int tid = threadIdx.x;

    float s = 0.f;
    for (int h = tid; h < H_; h += 256) {
        float z = q[h] * v[h];
        s += fabsf(z);
    }
    __shared__ float red[8];
#pragma unroll
    for (int off = 16; off; off >>= 1) s += __shfl_xor_sync(0xffffffffu, s, off);
    if ((tid & 31) == 0) red[tid >> 5] = s;
    __syncthreads();
    float tot = 0.f;
#pragma unroll
    for (int i = 0; i < 8; i++) tot += red[i];
    float inv = 1.f / fmaxf(sqrtf(tot), 1e-12f);

    for (int h = tid; h < H_; h += 256) {
        float z = q[h] * v[h];
        float sg = (z > 0.f) ? sqrtf(z) : -sqrtf(-z);
        o[h] = sg * inv;
    }
}

// ---------------------------------------------------------------------------
// Masked role attention (single head), one block per batch element.
// q/k/v packed in QKV3 rows of 3072: [q | k | v]
// ---------------------------------------------------------------------------
__global__ void role_att_kernel(const int* __restrict__ mask)
{
    int b = blockIdx.x;
    const float* base = g_scratch + OFF_QKV3 + (long)b * R_ * 3072;
    float*       ctx  = g_scratch + OFF_CTX  + (long)b * R_ * H_;

    __shared__ float sc[R_][R_];
    __shared__ float attn[R_][R_];
    int tid = threadIdx.x, wid = tid >> 5, lane = tid & 31;

    for (int p = wid; p < R_ * R_; p += 8) {
        int i = p / R_, j = p % R_;
        const float* qh = base + (long)i * 3072;
        const float* kh = base + (long)j * 3072 + 1024;
        float s = 0.f;
        for (int h = lane; h < H_; h += 32)
            s = fmaf(qh[h], kh[h], s);
#pragma unroll
        for (int o = 16; o; o >>= 1) s += __shfl_xor_sync(0xffffffffu, s, o);
        if (lane == 0) {
            bool valid = (i != j) && (mask[((long)b * R_ + i) * R_ + j] > 0);
            sc[i][j] = valid ? s * (1.f / 32.f) : -1e9f;
        }
    }
    __syncthreads();

    if (tid < R_ * R_) {
        int i = tid / R_, j = tid % R_;
        float mx = -1e30f;
        for (int jj = 0; jj < R_; jj++) mx = fmaxf(mx, sc[i][jj]);
        float sum = 0.f;
        for (int jj = 0; jj < R_; jj++) sum += expf(sc[i][jj] - mx);
        attn[i][j] = expf(sc[i][j] - mx) / sum;
    }
    __syncthreads();

    for (int idx = tid; idx < R_ * H_; idx += 256) {
        int i = idx / H_, h = idx % H_;
        float acc = 0.f;
#pragma unroll
        for (int j = 0; j < R_; j++)
            acc = fmaf(attn[i][j], base[(long)j * 3072 + 2048 + h], acc);
        ctx[idx] = acc;
    }
}

// ---------------------------------------------------------------------------
// cat = [neigh | rv]
// ---------------------------------------------------------------------------
__global__ void concat_kernel()
{
    long idx = (long)blockIdx.x * 256 + threadIdx.x;
    if (idx >= SZ_CAT) return;
    int col = (int)(idx % CATW);
    int n   = (int)(idx / CATW);
    float v = (col < H_) ? g_scratch[OFF_NEIGH + (long)n * H_ + col]
                         : g_scratch[OFF_RV + (long)n * TWO_E + (col - H_)];
    g_scratch[OFF_CAT + idx] = v;
}

// ---------------------------------------------------------------------------
// gated fusion
// ---------------------------------------------------------------------------
__global__ void combine_kernel()
{
    long idx = (long)blockIdx.x * 256 + threadIdx.x;
    if (idx >= SZ_H) return;
    float o2 = g_scratch[OFF_OUT2 + idx];
    float ov = g_scratch[OFF_OUTV + idx];
    float a0 = g_scratch[OFF_OUT + idx];
    float g  = 1.f / (1.f + expf(-(o2 + ov)));
    g_scratch[OFF_OUTF + idx] = (1.f - g) * ov + g * tanhf(o2 + a0);
}

// ---------------------------------------------------------------------------
// Launch sequence
// ---------------------------------------------------------------------------
extern "C" void kernel_launch(void* const* d_in, const int* in_sizes, int n_in,
                              void* d_out, int out_size)
{
    const float* v_org    = (const float*)d_in[0];
    const float* img_feat = (const float*)d_in[1];
    const int*   gt_verb  = (const int*)d_in[2];
    const int*   role_idx = (const int*)d_in[3];
    const int*   mask     = (const int*)d_in[4];
    const float* verb_t   = (const float*)d_in[5];
    const float* role_t   = (const float*)d_in[6];
    const float* qc_W = (const float*)d_in[7];   const float* qc_b = (const float*)d_in[8];
    const float* av_W = (const float*)d_in[9];   const float* av_b = (const float*)d_in[10];
    const float* aq_W = (const float*)d_in[11];  const float* aq_b = (const float*)d_in[12];
    const float* ao_W = (const float*)d_in[13];  const float* ao_b = (const float*)d_in[14];
    const float* vn_W = (const float*)d_in[15];  const float* vn_b = (const float*)d_in[16];
    const float* qn_W = (const float*)d_in[17];  const float* qn_b = (const float*)d_in[18];
    const float* Wq   = (const float*)d_in[19];
    const float* Wk   = (const float*)d_in[20];
    const float* Wv   = (const float*)d_in[21];
    const float* Wo   = (const float*)d_in[22];
    const float* uqc_W = (const float*)d_in[23]; const float* uqc_b = (const float*)d_in[24];
    const float* cls_W = (const float*)d_in[25]; const float* cls_b = (const float*)d_in[26];

    cudaFuncSetAttribute(mma_gemm_kernel<128>,
                         cudaFuncAttributeMaxDynamicSharedMemorySize, SMEM_128);
    cudaFuncSetAttribute(mma_gemm_kernel<64>,
                         cudaFuncAttributeMaxDynamicSharedMemorySize, SMEM_64);

    auto wc = [&](const float* W, int K, int N, int Kp, int Np, long off) {
        dim3 g(Kp / 32, Np / 32);
        wconv_kernel<<<g, dim3(32, 8)>>>(W, K, N, Kp, Np, off);
    };

    // launches 0-4
    transpose_kernel<<<(int)((SZ_IMG0 + 255) / 256), 256>>>(v_org);              // 0
    gather_rv_kernel<<<(int)((SZ_RV + 255) / 256), 256>>>(gt_verb, role_idx,
                                                          verb_t, role_t);       // 1
    wc(av_W,  512, 1024,  512, 1024, WOFF_AV);                                    // 2
    wc(qc_W,  600, 1024,  640, 1024, WOFF_QC);                                    // 3
    tgemm(img_feat, 0, WOFF_AV, av_b, -1, nullptr, OFF_V2,
          B_ * K_, 1024, 1024, 512, 512, 1);                                      // 4
    // launch 5 — the big V1 GEMM (profiled by ncu -s 5 -c 1)
    tgemm(nullptr, OFF_IMG0, WOFF_AV, av_b, -1, nullptr, OFF_V1,
          B_ * K_, 1024, 1024, 512, 512, 1);                                      // 5

    // remaining weight conversions
    wc(aq_W, 1024, 1024, 1024, 1024, WOFF_AQN);
    wc(qn_W, 1024, 1024, 1024, 1024, WOFF_AQN + 1024L * 1024);
    wc(vn_W,  512, 1024,  512, 1024, WOFF_VN);
    wc(Wq,   1024, 1024, 1024, 1024, WOFF_QKV);
    wc(Wk,   1024, 1024, 1024, 1024, WOFF_QKV + 1024L * 1024);
    wc(Wv,   1024, 1024, 1024, 1024, WOFF_QKV + 2048L * 1024);
    wc(Wo,   1024, 1024, 1024, 1024, WOFF_WO);
    wc(uqc_W, CATW, 1024, 1664, 1024, WOFF_UQC);
    wc(cls_W, 1024, NL_, 1024, 2048, WOFF_CLS);
    packb_kernel<<<8, 256>>>(aq_b, qn_b);

    // query chain
    tgemm(nullptr, OFF_RV, WOFF_QC, qc_b, -1, nullptr, OFF_QEMB,
          BR_, 1024, 1024, 600, 640, 1);
    tgemm(nullptr, OFF_QEMB, WOFF_AQN, nullptr, OFF_BIASAQN, nullptr, OFF_QAQR,
          BR_, 2048, 2048, 1024, 1024, 1);

    // attention 1 (spatial) and attention-verb (img_feat)
    att6_kernel<<<B_, 256>>>(OFF_V1, OFF_QAQR, 2048, ao_W, ao_b, nullptr, OFF_IMG0, OFF_VEMB1);
    att6_kernel<<<B_, 256>>>(OFF_V2, OFF_QAQR, 2048, ao_W, ao_b, img_feat, 0,      OFF_VEMB2);

    // fused VN over [VEMB1 ; VEMB2]  (M = 2*BR)
    tgemm(nullptr, OFF_VEMB1, WOFF_VN, vn_b, -1, nullptr, OFF_VREPR1,
          2 * BR_, 1024, 1024, 512, 512, 1);

    // fused MFB for OUT and OUTV (2*BR blocks)
    mfb_kernel<<<2 * BR_, 256>>>(OFF_QAQR + 1024, 2048, BR_, OFF_VREPR1, OFF_OUT);

    // role-node neighbour attention: fused QKV projection
    tgemm(nullptr, OFF_OUT, WOFF_QKV, nullptr, -1, nullptr, OFF_QKV3,
          BR_, 3072, 3072, 1024, 1024, 0);
    role_att_kernel<<<B_, 256>>>(mask);
    tgemm(nullptr, OFF_CTX, WOFF_WO, nullptr, -1, nullptr, OFF_NEIGH,
          BR_, 1024, 1024, 1024, 1024, 0);

    // updated query
    concat_kernel<<<(int)((SZ_CAT + 255) / 256), 256>>>();
    tgemm(nullptr, OFF_CAT, WOFF_UQC, uqc_b, -1, nullptr, OFF_UQ,
          BR_, 1024, 1024, CATW, 1664, 1);
    tgemm(nullptr, OFF_UQ, WOFF_AQN, nullptr, OFF_BIASAQN, nullptr, OFF_QAQR2,
          BR_, 2048, 2048, 1024, 1024, 1);

    // attention 2
    att6_kernel<<<B_, 256>>>(OFF_V1, OFF_QAQR2, 2048, ao_W, ao_b, nullptr, OFF_IMG0, OFF_VEMB3);
    tgemm(nullptr, OFF_VEMB3, WOFF_VN, vn_b, -1, nullptr, OFF_VREPR2,
          BR_, 1024, 1024, 512, 512, 1);
    mfb_kernel<<<BR_, 256>>>(OFF_QAQR2 + 1024, 2048, BR_, OFF_VREPR2, OFF_OUT2);

    // gated fusion
    combine_kernel<<<(int)((SZ_H + 255) / 256), 256>>>();

    // classifier -> d_out
    tgemm(nullptr, OFF_OUTF, WOFF_CLS, cls_b, -1, (float*)d_out, 0,
          BR_, NL_, 2048, 1024, 1024, 0);
}

// round 6
// speedup vs baseline: 3.2964x; 1.0367x over previous
#include <cuda_runtime.h>
#include <cuda_bf16.h>
#include <cstdint>
#include <math.h>

// ---------------------------------------------------------------------------
// Problem dims
// ---------------------------------------------------------------------------
constexpr int B_   = 256;
constexpr int R_   = 6;
constexpr int K_   = 49;
constexpr int C_   = 512;
constexpr int H_   = 1024;
constexpr int E_   = 300;
constexpr int BR_  = B_ * R_;          // 1536
constexpr int NL_  = 2001;
constexpr int TWO_E = 2 * E_;          // 600
constexpr int CATW  = H_ + TWO_E;      // 1624

// ---------------------------------------------------------------------------
// fp32 scratch
// ---------------------------------------------------------------------------
constexpr long SZ_IMG0 = (long)B_ * K_ * C_;   // 6422528
constexpr long SZ_V    = (long)B_ * K_ * H_;
constexpr long SZ_RV   = (long)BR_ * TWO_E;
constexpr long SZ_H    = (long)BR_ * H_;
constexpr long SZ_2H   = (long)BR_ * 2048;
constexpr long SZ_3H   = (long)BR_ * 3072;

constexpr long OFF_IMG0  = 0;
constexpr long OFF_V1    = OFF_IMG0  + SZ_IMG0;
constexpr long OFF_V2    = OFF_V1    + SZ_V;
constexpr long OFF_RV    = OFF_V2    + SZ_V;
constexpr long OFF_QAQR  = OFF_RV    + SZ_RV;     // [BR,2048] = [qa|qrepr]
constexpr long OFF_VREPR1= OFF_QAQR  + SZ_2H;     // [2BR,1024] (VREPR1;VREPRV)
constexpr long OFF_OUT   = OFF_VREPR1+ 2*SZ_H;    // [2BR,1024] (OUT;OUTV)
constexpr long OFF_QKV3  = OFF_OUT   + 2*SZ_H;    // [BR,3072]
constexpr long OFF_NEIGH = OFF_QKV3  + SZ_3H;
constexpr long OFF_QAQR2 = OFF_NEIGH + SZ_H;
constexpr long OFF_VREPR2= OFF_QAQR2 + SZ_2H;
constexpr long OFF_OUT2  = OFF_VREPR2+ SZ_H;
constexpr long OFF_BIASAQN = OFF_OUT2 + SZ_H;     // 2048 floats
constexpr long SCRATCH_TOTAL = OFF_BIASAQN + 2048;

__device__ float g_scratch[SCRATCH_TOTAL];

// ---------------------------------------------------------------------------
// bf16 ACTIVATION planes (hi at off, lo at off+ATOTAL). Zero-initialized:
// pad columns are never written -> stay zero -> no K guards in GEMM.
// ---------------------------------------------------------------------------
constexpr long ABF_IMG0  = 0;                          // [12544][512]
constexpr long ABF_IMGF  = ABF_IMG0  + 12544L * 512;   // [12544][512]
constexpr long ABF_RV    = ABF_IMGF  + 12544L * 512;   // [1536][640]
constexpr long ABF_QEMB  = ABF_RV    + 1536L * 640;    // [1536][1024]
constexpr long ABF_VEMB12= ABF_QEMB  + 1536L * 1024;   // [3072][512]
constexpr long ABF_VEMB3 = ABF_VEMB12+ 3072L * 512;    // [1536][512]
constexpr long ABF_OUT   = ABF_VEMB3 + 1536L * 512;    // [3072][1024]
constexpr long ABF_CTX   = ABF_OUT   + 3072L * 1024;   // [1536][1024]
constexpr long ABF_CAT   = ABF_CTX   + 1536L * 1024;   // [1536][1664]
constexpr long ABF_UQ    = ABF_CAT   + 1536L * 1664;   // [1536][1024]
constexpr long ABF_OUTF  = ABF_UQ    + 1536L * 1024;   // [1536][1024]
constexpr long ATOTAL    = ABF_OUTF  + 1536L * 1024;

__device__ __align__(256) __nv_bfloat16 g_abf[2 * ATOTAL];

// ---------------------------------------------------------------------------
// bf16 WEIGHT planes (transposed [Npad][Kpad], hi at off, lo at off+WTOTAL)
// ---------------------------------------------------------------------------
constexpr long WOFF_QC  = 0;                           // [1024][640]
constexpr long WOFF_AV  = WOFF_QC  + 1024L * 640;      // [1024][512]
constexpr long WOFF_AQN = WOFF_AV  + 1024L * 512;      // [2048][1024]
constexpr long WOFF_VN  = WOFF_AQN + 2048L * 1024;     // [1024][512]
constexpr long WOFF_QKV = WOFF_VN  + 1024L * 512;      // [3072][1024]
constexpr long WOFF_WO  = WOFF_QKV + 3072L * 1024;     // [1024][1024]
constexpr long WOFF_UQC = WOFF_WO  + 1024L * 1024;     // [1024][1664]
constexpr long WOFF_CLS = WOFF_UQC + 1024L * 1664;     // [2048][1024]
constexpr long WTOTAL   = WOFF_CLS + 2048L * 1024;

__device__ __align__(256) __nv_bfloat16 g_wbf[2 * WTOTAL];

// ---------------------------------------------------------------------------
// helpers
// ---------------------------------------------------------------------------
__device__ __forceinline__ uint32_t smem_u32(const void* p) {
    uint32_t a;
    asm("{ .reg .u64 t; cvta.to.shared.u64 t, %1; cvt.u32.u64 %0, t; }" : "=r"(a) : "l"(p));
    return a;
}
__device__ __forceinline__ void stsplit(long base, float v) {
    __nv_bfloat16 h = __float2bfloat16(v);
    g_abf[base] = h;
    g_abf[base + ATOTAL] = __float2bfloat16(v - __bfloat162float(h));
}
__device__ __forceinline__ void ldm_x4(uint32_t* r, uint32_t addr) {
    asm volatile("ldmatrix.sync.aligned.m8n8.x4.shared.b16 {%0,%1,%2,%3}, [%4];"
                 : "=r"(r[0]), "=r"(r[1]), "=r"(r[2]), "=r"(r[3]) : "r"(addr));
}
__device__ __forceinline__ void mma16816(float* c, const uint32_t* a, const uint32_t* b) {
    asm volatile(
        "mma.sync.aligned.m16n8k16.row.col.f32.bf16.bf16.f32 "
        "{%0,%1,%2,%3}, {%4,%5,%6,%7}, {%8,%9}, {%0,%1,%2,%3};"
        : "+f"(c[0]), "+f"(c[1]), "+f"(c[2]), "+f"(c[3])
        : "r"(a[0]), "r"(a[1]), "r"(a[2]), "r"(a[3]), "r"(b[0]), "r"(b[1]));
}
__device__ __forceinline__ void cpa16(uint32_t s, const void* g) {
    asm volatile("cp.async.cg.shared.global [%0], [%1], 16;" :: "r"(s), "l"(g));
}
#define CP_COMMIT() asm volatile("cp.async.commit_group;" ::: "memory")
#define CP_WAIT0()  asm volatile("cp.async.wait_group 0;" ::: "memory")

// ---------------------------------------------------------------------------
// megaconv: ALL weight transposes + bf16 splits in ONE launch
// ---------------------------------------------------------------------------
struct WAll {
    const float* W[11];
    int K[11], N[11], tilesK[11];
    int pre[12];
    long off[11];
};

__global__ void megaconv_kernel(WAll P)
{
    __shared__ float tile[32][33];
    int bx = blockIdx.x;
    int w = 0;
    while (bx >= P.pre[w + 1]) w++;
    int tix = bx - P.pre[w];
    int tK  = P.tilesK[w];
    int k0  = (tix % tK) * 32;
    int n0  = (tix / tK) * 32;
    int K = P.K[w], N = P.N[w], Kp = tK * 32;
    const float* W = P.W[w];
    long off = P.off[w];

    int tx = threadIdx.x, ty = threadIdx.y;
#pragma unroll
    for (int i = 0; i < 32; i += 8) {
        int k = k0 + ty + i, n = n0 + tx;
        tile[ty + i][tx] = (k < K && n < N) ? W[(size_t)k * N + n] : 0.f;
    }
    __syncthreads();
#pragma unroll
    for (int i = 0; i < 32; i += 8) {
        int n = n0 + ty + i, k = k0 + tx;
        float v = tile[tx][ty + i];
        __nv_bfloat16 h = __float2bfloat16(v);
        __nv_bfloat16 l = __float2bfloat16(v - __bfloat162float(h));
        long o = off + (long)n * Kp + k;
        g_wbf[o] = h;
        g_wbf[o + WTOTAL] = l;
    }
}

// img_feat fp32 -> bf16 split; plus pack [aq_b|qn_b] bias
__global__ void convf_kernel(const float* __restrict__ imgf,
                             const float* __restrict__ b0,
                             const float* __restrict__ b1)
{
    long idx = (long)blockIdx.x * 256 + threadIdx.x;
    if (idx < SZ_IMG0) {
        stsplit(ABF_IMGF + idx, imgf[idx]);
    } else {
        long i = idx - SZ_IMG0;
        if (i < 1024)      g_scratch[OFF_BIASAQN + i] = b0[i];
        else if (i < 2048) g_scratch[OFF_BIASAQN + i] = b1[i - 1024];
    }
}

// ---------------------------------------------------------------------------
// HMMA bf16-split GEMM, all operands pre-split bf16, pure cp.async mainloop.
// C[M,N] = act(A @ W + bias); out fp32 (ptr/scratch) or bf16-split (g_abf).
// ---------------------------------------------------------------------------
template<int BM>
__global__ __launch_bounds__(256, 2)
void mma_gemm_kernel(long aOff, long wOff,
                     const float* __restrict__ biasPtr, long biasOff,
                     float* CExt, long offC, long offCbf,
                     int M, int N, int Kp, int act)
{
    constexpr int BN = 128, BKP = 40;
    constexpr int MI  = BM / 32;
    constexpr int NT  = 4;
    constexpr int ASZ = BM * BKP;            // bf16 elems
    constexpr int BSZ = BN * BKP;
    constexpr int STG = 2 * ASZ + 2 * BSZ;
    constexpr uint32_t ASZ2 = ASZ * 2, BSZ2 = BSZ * 2;

    extern __shared__ __align__(16) __nv_bfloat16 sm[];
    const __nv_bfloat16* Ahp = g_abf + aOff;
    const __nv_bfloat16* Alp = g_abf + aOff + ATOTAL;
    const __nv_bfloat16* Bwh = g_wbf + wOff;
    const __nv_bfloat16* Bwl = g_wbf + wOff + WTOTAL;
    const float* bias = biasPtr ? biasPtr
                      : (biasOff >= 0 ? (const float*)(g_scratch + biasOff) : nullptr);

    const int tid  = threadIdx.x;
    const int wid  = tid >> 5, lane = tid & 31;
    const int brow = blockIdx.y * BM, bcol = blockIdx.x * BN;
    const int wm   = (wid >> 2) * (BM / 2);
    const int wn   = (wid & 3) * 32;
    const uint32_t sb = smem_u32(sm);

    auto cpAll = [&](int t, int s) {
        const uint32_t st = sb + (uint32_t)(s * STG) * 2;
#pragma unroll
        for (int l = 0; l < BM / 64; l++) {
            int idx = tid + l * 256;
            int row = idx >> 2, seg = idx & 3;
            size_t go = (size_t)(brow + row) * Kp + t * 32 + seg * 8;
            uint32_t so = (uint32_t)(row * BKP + seg * 8) * 2;
            cpa16(st + so,        Ahp + go);
            cpa16(st + ASZ2 + so, Alp + go);
        }
#pragma unroll
        for (int l = 0; l < 2; l++) {
            int idx = tid + l * 256;
            int row = idx >> 2, seg = idx & 3;
            size_t go = (size_t)(bcol + row) * Kp + t * 32 + seg * 8;
            uint32_t so = (uint32_t)(row * BKP + seg * 8) * 2;
            cpa16(st + 2 * ASZ2 + so,        Bwh + go);
            cpa16(st + 2 * ASZ2 + BSZ2 + so, Bwl + go);
        }
    };

    float acc[MI][NT][4];
#pragma unroll
    for (int i = 0; i < MI; i++)
#pragma unroll
        for (int j = 0; j < NT; j++)
#pragma unroll
            for (int q = 0; q < 4; q++) acc[i][j][q] = 0.f;

    const int nCh = Kp / 32;

    cpAll(0, 0); CP_COMMIT();
    CP_WAIT0();
    __syncthreads();

    const int aRow = (lane & 7) + ((lane >> 3) & 1) * 8;
    const int aCol = (lane >> 4) * 8;
    const int bRow = (lane & 7) + ((lane >> 4) & 1) * 8;
    const int bCol = ((lane >> 3) & 1) * 8;

    for (int t = 0; t < nCh; t++) {
        const int s = t & 1;
        if (t + 1 < nCh) { cpAll(t + 1, s ^ 1); CP_COMMIT(); }

        const uint32_t ahB = sb + (uint32_t)(s * STG) * 2;
        const uint32_t alB = ahB + ASZ2;
        const uint32_t bhB = alB + ASZ2;
        const uint32_t blB = bhB + BSZ2;

#pragma unroll
        for (int ks = 0; ks < 2; ks++) {
            uint32_t ah[MI][4], al[MI][4];
#pragma unroll
            for (int mi = 0; mi < MI; mi++) {
                uint32_t off = (uint32_t)((wm + mi * 16 + aRow) * BKP + ks * 16 + aCol) * 2;
                ldm_x4(ah[mi], ahB + off);
                ldm_x4(al[mi], alB + off);
            }
            uint32_t bh[NT][2], bl[NT][2];
#pragma unroll
            for (int bt = 0; bt < NT / 2; bt++) {
                uint32_t off = (uint32_t)((wn + bt * 16 + bRow) * BKP + ks * 16 + bCol) * 2;
                uint32_t r[4];
                ldm_x4(r, bhB + off);
                bh[2 * bt][0] = r[0]; bh[2 * bt][1] = r[1];
                bh[2 * bt + 1][0] = r[2]; bh[2 * bt + 1][1] = r[3];
                ldm_x4(r, blB + off);
                bl[2 * bt][0] = r[0]; bl[2 * bt][1] = r[1];
                bl[2 * bt + 1][0] = r[2]; bl[2 * bt + 1][1] = r[3];
            }
#pragma unroll
            for (int mi = 0; mi < MI; mi++)
#pragma unroll
                for (int ni = 0; ni < NT; ni++) {
                    mma16816(acc[mi][ni], ah[mi], bh[ni]);
                    mma16816(acc[mi][ni], ah[mi], bl[ni]);
                    mma16816(acc[mi][ni], al[mi], bh[ni]);
                }
        }

        if (t + 1 < nCh) {
            CP_WAIT0();
            __syncthreads();
        }
    }

    // epilogue
    float* C = CExt ? CExt : (g_scratch + offC);
#pragma unroll
    for (int mi = 0; mi < MI; mi++) {
#pragma unroll
        for (int ni = 0; ni < NT; ni++) {
            int r0 = brow + wm + mi * 16 + (lane >> 2);
            int c0 = bcol + wn + ni * 8 + 2 * (lane & 3);
#pragma unroll
            for (int half = 0; half < 2; half++) {
                int gr = r0 + half * 8;
                float v0 = acc[mi][ni][2 * half + 0];
                float v1 = acc[mi][ni][2 * half + 1];
                if (offCbf >= 0) {
                    // bf16-split output (N even, no guards needed: N==Np)
                    if (bias) { v0 += bias[c0]; v1 += bias[c0 + 1]; }
                    if (act)  { v0 = fmaxf(v0, 0.f); v1 = fmaxf(v1, 0.f); }
                    __nv_bfloat16 h0 = __float2bfloat16(v0);
                    __nv_bfloat16 h1 = __float2bfloat16(v1);
                    __nv_bfloat16 l0 = __float2bfloat16(v0 - __bfloat162float(h0));
                    __nv_bfloat16 l1 = __float2bfloat16(v1 - __bfloat162float(h1));
                    long o = offCbf + (long)gr * N + c0;
                    uint32_t hp = (uint32_t)__bfloat16_as_ushort(h0)
                                | ((uint32_t)__bfloat16_as_ushort(h1) << 16);
                    uint32_t lp = (uint32_t)__bfloat16_as_ushort(l0)
                                | ((uint32_t)__bfloat16_as_ushort(l1) << 16);
                    *(uint32_t*)&g_abf[o] = hp;
                    *(uint32_t*)&g_abf[o + ATOTAL] = lp;
                } else {
                    if (c0 < N) {
                        float o = v0 + (bias ? bias[c0] : 0.f);
                        if (act) o = fmaxf(o, 0.f);
                        C[(size_t)gr * N + c0] = o;
                    }
                    if (c0 + 1 < N) {
                        float o = v1 + (bias ? bias[c0 + 1] : 0.f);
                        if (act) o = fmaxf(o, 0.f);
                        C[(size_t)gr * N + c0 + 1] = o;
                    }
                }
            }
        }
    }
}

constexpr int SMEM_128 = 2 * (2 * 128 * 40 + 2 * 128 * 40) * 2;  // 81920 B
constexpr int SMEM_64  = 2 * (2 * 64 * 40 + 2 * 128 * 40) * 2;   // 61440 B

static inline void tgemm(long aOff, long wOff, const float* bias, long biasOff,
                         float* CExt, long offC, long offCbf,
                         int M, int N, int Np, int Kp, int act)
{
    if (M >= 4096) {
        dim3 grid(Np / 128, M / 128);
        mma_gemm_kernel<128><<<grid, 256, SMEM_128>>>(aOff, wOff, bias, biasOff,
                                                      CExt, offC, offCbf, M, N, Kp, act);
    } else {
        dim3 grid(Np / 128, M / 64);
        mma_gemm_kernel<64><<<grid, 256, SMEM_64>>>(aOff, wOff, bias, biasOff,
                                                    CExt, offC, offCbf, M, N, Kp, act);
    }
}

// ---------------------------------------------------------------------------
// img0[b,k,c] = v_org[b,c,k]  (fp32 for att6 + bf16 split for GEMM)
// ---------------------------------------------------------------------------
__global__ void transpose_kernel(const float* __restrict__ v_org)
{
    long idx = (long)blockIdx.x * 256 + threadIdx.x;
    if (idx >= SZ_IMG0) return;
    int  c = (int)(idx % C_);
    long t = idx / C_;
    int  k = (int)(t % K_);
    int  b = (int)(t / K_);
    float v = v_org[((long)b * C_ + c) * K_ + k];
    g_scratch[OFF_IMG0 + idx] = v;
    stsplit(ABF_IMG0 + idx, v);
}

// ---------------------------------------------------------------------------
// rv gather (fp32 for concat + bf16 split for QEMB gemm, row stride 640)
// ---------------------------------------------------------------------------
__global__ void gather_rv_kernel(const int* __restrict__ gt_verb,
                                 const int* __restrict__ role_idx,
                                 const float* __restrict__ vt,
                                 const float* __restrict__ rt)
{
    long idx = (long)blockIdx.x * 256 + threadIdx.x;
    if (idx >= SZ_RV) return;
    int e = (int)(idx % TWO_E);
    int n = (int)(idx / TWO_E);
    int b = n / R_;
    float val = (e < E_) ? vt[(long)gt_verb[b] * E_ + e]
                         : rt[(long)role_idx[n] * E_ + (e - E_)];
    g_scratch[OFF_RV + idx] = val;
    stsplit(ABF_RV + (long)n * 640 + e, val);
}

// ---------------------------------------------------------------------------
// Visual attention (block per batch element, 6 roles) -> bf16 split vemb
// ---------------------------------------------------------------------------
__global__ __launch_bounds__(256) void att6_kernel(
    long offV, long offQA, int qStride,
    const float* __restrict__ aoW, const float* __restrict__ aoB,
    const float* __restrict__ imgPtr, long offImg, long abfOut)
{
    int b  = blockIdx.x;
    int n0 = b * R_;
    const float* V   = g_scratch + offV + (long)b * K_ * H_;
    const float* img = imgPtr ? (imgPtr + (long)b * K_ * C_)
                              : (g_scratch + offImg + (long)b * K_ * C_);

    __shared__ float qa[R_][H_];
    __shared__ float attw[R_][K_ + 1];

    int tid = threadIdx.x, wid = tid >> 5, lane = tid & 31;

    for (int idx = tid; idx < R_ * H_; idx += 256) {
        int r = idx / H_, h = idx % H_;
        qa[r][h] = g_scratch[offQA + (long)(n0 + r) * qStride + h] * aoW[h];
    }
    __syncthreads();

    for (int k = wid; k < K_; k += 8) {
        const float* vk = V + (long)k * H_;
        float s0=0,s1=0,s2=0,s3=0,s4=0,s5=0;
        for (int h = lane; h < H_; h += 32) {
            float v = vk[h];
            s0 = fmaf(v, qa[0][h], s0); s1 = fmaf(v, qa[1][h], s1);
            s2 = fmaf(v, qa[2][h], s2); s3 = fmaf(v, qa[3][h], s3);
            s4 = fmaf(v, qa[4][h], s4); s5 = fmaf(v, qa[5][h], s5);
        }
#pragma unroll
        for (int o = 16; o; o >>= 1) {
            s0 += __shfl_xor_sync(0xffffffffu, s0, o);
            s1 += __shfl_xor_sync(0xffffffffu, s1, o);
            s2 += __shfl_xor_sync(0xffffffffu, s2, o);
            s3 += __shfl_xor_sync(0xffffffffu, s3, o);
            s4 += __shfl_xor_sync(0xffffffffu, s4, o);
            s5 += __shfl_xor_sync(0xffffffffu, s5, o);
        }
        if (lane == 0) {
            float ab = aoB[0];
            attw[0][k] = s0 + ab; attw[1][k] = s1 + ab; attw[2][k] = s2 + ab;
            attw[3][k] = s3 + ab; attw[4][k] = s4 + ab; attw[5][k] = s5 + ab;
        }
    }
    __syncthreads();

    if (tid < R_) {
        float mx = -1e30f;
        for (int k = 0; k < K_; k++) mx = fmaxf(mx, attw[tid][k]);
        float sum = 0.f;
        for (int k = 0; k < K_; k++) sum += expf(attw[tid][k] - mx);
        float inv = 1.f / sum;
        for (int k = 0; k < K_; k++) attw[tid][k] = expf(attw[tid][k] - mx) * inv;
    }
    __syncthreads();

    for (int c = tid; c < C_; c += 256) {
        float a0=0,a1=0,a2=0,a3=0,a4=0,a5=0;
#pragma unroll 7
        for (int k = 0; k < K_; k++) {
            float f = img[(long)k * C_ + c];
            a0 = fmaf(attw[0][k], f, a0); a1 = fmaf(attw[1][k], f, a1);
            a2 = fmaf(attw[2][k], f, a2); a3 = fmaf(attw[3][k], f, a3);
            a4 = fmaf(attw[4][k], f, a4); a5 = fmaf(attw[5][k], f, a5);
        }
        long base = abfOut + (long)n0 * C_ + c;
        stsplit(base,          a0); stsplit(base + C_,     a1);
        stsplit(base + 2 * C_, a2); stsplit(base + 3 * C_, a3);
        stsplit(base + 4 * C_, a4); stsplit(base + 5 * C_, a5);
    }
}

// ---------------------------------------------------------------------------
// MFB pool: fp32 out + optional bf16 split (row stride 1024)
// ---------------------------------------------------------------------------
__global__ void mfb_kernel(long offQ, int qStride, int qWrap,
                           long offV, long offOut, long abfOut)
{
    int n = blockIdx.x;
    const float* q = g_scratch + offQ   + (long)(n % qWrap) * qStride;
    const float* v = g_scratch + offV   + (long)n * H_;
    float*       o = g_scratch + offOut + (long)n * H_;
    int tid = threadIdx.x;

    float s = 0.f;
    for (int h = tid; h < H_; h += 256) {
        float z = q[h] * v[h];
        s += fabsf(z);
    }
    __shared__ float red[8];
#pragma unroll
    for (int off = 16; off; off >>= 1) s += __shfl_xor_sync(0xffffffffu, s, off);
    if ((tid & 31) == 0) red[tid >> 5] = s;
    __syncthreads();
    float tot = 0.f;
#pragma unroll
    for (int i = 0; i < 8; i++) tot += red[i];
    float inv = 1.f / fmaxf(sqrtf(tot), 1e-12f);

    for (int h = tid; h < H_; h += 256) {
        float z = q[h] * v[h];
        float sg = (z > 0.f) ? sqrtf(z) : -sqrtf(-z);
        float r = sg * inv;
        o[h] = r;
        if (abfOut >= 0) stsplit(abfOut + (long)n * H_ + h, r);
    }
}

// ---------------------------------------------------------------------------
// Masked role attention -> ctx as bf16 split (feeds WO gemm only)
// ---------------------------------------------------------------------------
__global__ void role_att_kernel(const int* __restrict__ mask)
{
    int b = blockIdx.x;
    const float* base = g_scratch + OFF_QKV3 + (long)b * R_ * 3072;

    __shared__ float sc[R_][R_];
    __shared__ float attn[R_][R_];
    int tid = threadIdx.x, wid = tid >> 5, lane = tid & 31;

    for (int p = wid; p < R_ * R_; p += 8) {
        int i = p / R_, j = p % R_;
        const float* qh = base + (long)i * 3072;
        const float* kh = base + (long)j * 3072 + 1024;
        float s = 0.f;
        for (int h = lane; h < H_; h += 32)
            s = fmaf(qh[h], kh[h], s);
#pragma unroll
        for (int o = 16; o; o >>= 1) s += __shfl_xor_sync(0xffffffffu, s, o);
        if (lane == 0) {
            bool valid = (i != j) && (mask[((long)b * R_ + i) * R_ + j] > 0);
            sc[i][j] = valid ? s * (1.f / 32.f) : -1e9f;
        }
    }
    __syncthreads();

    if (tid < R_ * R_) {
        int i = tid / R_, j = tid % R_;
        float mx = -1e30f;
        for (int jj = 0; jj < R_; jj++) mx = fmaxf(mx, sc[i][jj]);
        float sum = 0.f;
        for (int jj = 0; jj < R_; jj++) sum += expf(sc[i][jj] - mx);
        attn[i][j] = expf(sc[i][j] - mx) / sum;
    }
    __syncthreads();

    for (int idx = tid; idx < R_ * H_; idx += 256) {
        int i = idx / H_, h = idx % H_;
        float acc = 0.f;
#pragma unroll
        for (int j = 0; j < R_; j++)
            acc = fmaf(attn[i][j], base[(long)j * 3072 + 2048 + h], acc);
        stsplit(ABF_CTX + (long)(b * R_ + i) * H_ + h, acc);
    }
}

// ---------------------------------------------------------------------------
// cat = [neigh | rv] -> bf16 split only (stride 1664; pad cols stay zero)
// ---------------------------------------------------------------------------
__global__ void concat_kernel()
{
    long idx = (long)blockIdx.x * 256 + threadIdx.x;
    if (idx >= (long)BR_ * CATW) return;
    int col = (int)(idx % CATW);
    int n   = (int)(idx / CATW);
    float v = (col < H_) ? g_scratch[OFF_NEIGH + (long)n * H_ + col]
                         : g_scratch[OFF_RV + (long)n * TWO_E + (col - H_)];
    stsplit(ABF_CAT + (long)n * 1664 + col, v);
}

// ---------------------------------------------------------------------------
// gated fusion -> bf16 split only (feeds classifier)
// ---------------------------------------------------------------------------
__global__ void combine_kernel()
{
    long idx = (long)blockIdx.x * 256 + threadIdx.x;
    if (idx >= SZ_H) return;
    float o2 = g_scratch[OFF_OUT2 + idx];
    float ov = g_scratch[OFF_OUT + SZ_H + idx];
    float a0 = g_scratch[OFF_OUT + idx];
    float g  = 1.f / (1.f + expf(-(o2 + ov)));
    stsplit(ABF_OUTF + idx, (1.f - g) * ov + g * tanhf(o2 + a0));
}

// ---------------------------------------------------------------------------
// Launch sequence
// ---------------------------------------------------------------------------
extern "C" void kernel_launch(void* const* d_in, const int* in_sizes, int n_in,
                              void* d_out, int out_size)
{
    const float* v_org    = (const float*)d_in[0];
    const float* img_feat = (const float*)d_in[1];
    const int*   gt_verb  = (const int*)d_in[2];
    const int*   role_idx = (const int*)d_in[3];
    const int*   mask     = (const int*)d_in[4];
    const float* verb_t   = (const float*)d_in[5];
    const float* role_t   = (const float*)d_in[6];
    const float* qc_W = (const float*)d_in[7];   const float* qc_b = (const float*)d_in[8];
    const float* av_W = (const float*)d_in[9];   const float* av_b = (const float*)d_in[10];
    const float* aq_W = (const float*)d_in[11];  const float* aq_b = (const float*)d_in[12];
    const float* ao_W = (const float*)d_in[13];  const float* ao_b = (const float*)d_in[14];
    const float* vn_W = (const float*)d_in[15];  const float* vn_b = (const float*)d_in[16];
    const float* qn_W = (const float*)d_in[17];  const float* qn_b = (const float*)d_in[18];
    const float* Wq   = (const float*)d_in[19];
    const float* Wk   = (const float*)d_in[20];
    const float* Wv   = (const float*)d_in[21];
    const float* Wo   = (const float*)d_in[22];
    const float* uqc_W = (const float*)d_in[23]; const float* uqc_b = (const float*)d_in[24];
    const float* cls_W = (const float*)d_in[25]; const float* cls_b = (const float*)d_in[26];

    cudaFuncSetAttribute(mma_gemm_kernel<128>,
                         cudaFuncAttributeMaxDynamicSharedMemorySize, SMEM_128);
    cudaFuncSetAttribute(mma_gemm_kernel<64>,
                         cudaFuncAttributeMaxDynamicSharedMemorySize, SMEM_64);

    // megaconv descriptor table
    WAll P;
    const float* Ws[11] = {qc_W, av_W, aq_W, qn_W, vn_W, Wq, Wk, Wv, Wo, uqc_W, cls_W};
    int  Ks[11]  = {600, 512, 1024, 1024, 512, 1024, 1024, 1024, 1024, CATW, 1024};
    int  Ns[11]  = {1024,1024,1024, 1024, 1024,1024, 1024, 1024, 1024, 1024, NL_};
    int  tK[11]  = {20,  16,  32,   32,   16,  32,   32,   32,   32,   52,   32};
    int  Nps[11] = {1024,1024,1024, 1024, 1024,1024, 1024, 1024, 1024, 1024, 2048};
    long offs[11]= {WOFF_QC, WOFF_AV, WOFF_AQN, WOFF_AQN + 1024L * 1024, WOFF_VN,
                    WOFF_QKV, WOFF_QKV + 1024L * 1024, WOFF_QKV + 2048L * 1024,
                    WOFF_WO, WOFF_UQC, WOFF_CLS};
    int pre = 0;
    for (int i = 0; i < 11; i++) {
        P.W[i] = Ws[i]; P.K[i] = Ks[i]; P.N[i] = Ns[i];
        P.tilesK[i] = tK[i]; P.off[i] = offs[i];
        P.pre[i] = pre;
        pre += tK[i] * (Nps[i] / 32);
    }
    P.pre[11] = pre;   // 11520

    // 0,1,2 — prep; 3 — V1 GEMM (profiled slot)
    transpose_kernel<<<(int)((SZ_IMG0 + 255) / 256), 256>>>(v_org);
    gather_rv_kernel<<<(int)((SZ_RV + 255) / 256), 256>>>(gt_verb, role_idx, verb_t, role_t);
    megaconv_kernel<<<pre, dim3(32, 8)>>>(P);
    tgemm(ABF_IMG0, WOFF_AV, av_b, -1, nullptr, OFF_V1, -1,
          B_ * K_, 1024, 1024, 512, 1);
    convf_kernel<<<(int)((SZ_IMG0 + 2048 + 255) / 256), 256>>>(img_feat, aq_b, qn_b);
    tgemm(ABF_IMGF, WOFF_AV, av_b, -1, nullptr, OFF_V2, -1,
          B_ * K_, 1024, 1024, 512, 1);

    // query chain (QEMB -> bf16 only)
    tgemm(ABF_RV, WOFF_QC, qc_b, -1, nullptr, 0, ABF_QEMB,
          BR_, 1024, 1024, 640, 1);
    tgemm(ABF_QEMB, WOFF_AQN, nullptr, OFF_BIASAQN, nullptr, OFF_QAQR, -1,
          BR_, 2048, 2048, 1024, 1);

    // attention 1 + attention-verb
    att6_kernel<<<B_, 256>>>(OFF_V1, OFF_QAQR, 2048, ao_W, ao_b, nullptr, OFF_IMG0, ABF_VEMB12);
    att6_kernel<<<B_, 256>>>(OFF_V2, OFF_QAQR, 2048, ao_W, ao_b, img_feat, 0,
                             ABF_VEMB12 + (long)BR_ * 512);

    // fused VN over [VEMB1;VEMB2]
    tgemm(ABF_VEMB12, WOFF_VN, vn_b, -1, nullptr, OFF_VREPR1, -1,
          2 * BR_, 1024, 1024, 512, 1);

    // fused MFB (OUT rows get bf16 split for QKV gemm)
    mfb_kernel<<<2 * BR_, 256>>>(OFF_QAQR + 1024, 2048, BR_, OFF_VREPR1, OFF_OUT, ABF_OUT);

    // role-node neighbour attention
    tgemm(ABF_OUT, WOFF_QKV, nullptr, -1, nullptr, OFF_QKV3, -1,
          BR_, 3072, 3072, 1024, 0);
    role_att_kernel<<<B_, 256>>>(mask);
    tgemm(ABF_CTX, WOFF_WO, nullptr, -1, nullptr, OFF_NEIGH, -1,
          BR_, 1024, 1024, 1024, 0);

    // updated query
    concat_kernel<<<(int)(((long)BR_ * CATW + 255) / 256), 256>>>();
    tgemm(ABF_CAT, WOFF_UQC, uqc_b, -1, nullptr, 0, ABF_UQ,
          BR_, 1024, 1024, 1664, 1);
    tgemm(ABF_UQ, WOFF_AQN, nullptr, OFF_BIASAQN, nullptr, OFF_QAQR2, -1,
          BR_, 2048, 2048, 1024, 1);

    // attention 2
    att6_kernel<<<B_, 256>>>(OFF_V1, OFF_QAQR2, 2048, ao_W, ao_b, nullptr, OFF_IMG0, ABF_VEMB3);
    tgemm(ABF_VEMB3, WOFF_VN, vn_b, -1, nullptr, OFF_VREPR2, -1,
          BR_, 1024, 1024, 512, 1);
    mfb_kernel<<<BR_, 256>>>(OFF_QAQR2 + 1024, 2048, BR_, OFF_VREPR2, OFF_OUT2, -1);

    // gated fusion
    combine_kernel<<<(int)((SZ_H + 255) / 256), 256>>>();

    // classifier -> d_out
    tgemm(ABF_OUTF, WOFF_CLS, cls_b, -1, (float*)d_out, 0, -1,
          BR_, NL_, 2048, 1024, 0);
}

// round 7
// speedup vs baseline: 3.5196x; 1.0677x over previous
#include <cuda_runtime.h>
#include <cuda_bf16.h>
#include <cstdint>
#include <math.h>

// ---------------------------------------------------------------------------
// Problem dims
// ---------------------------------------------------------------------------
constexpr int B_   = 256;
constexpr int R_   = 6;
constexpr int K_   = 49;
constexpr int C_   = 512;
constexpr int H_   = 1024;
constexpr int E_   = 300;
constexpr int BR_  = B_ * R_;          // 1536
constexpr int NL_  = 2001;
constexpr int TWO_E = 2 * E_;          // 600
constexpr int CATW  = H_ + TWO_E;      // 1624

// ---------------------------------------------------------------------------
// fp32 scratch
// ---------------------------------------------------------------------------
constexpr long SZ_IMG0 = (long)B_ * K_ * C_;   // 6422528
constexpr long SZ_V    = (long)B_ * K_ * H_;
constexpr long SZ_RV   = (long)BR_ * TWO_E;
constexpr long SZ_H    = (long)BR_ * H_;
constexpr long SZ_2H   = (long)BR_ * 2048;
constexpr long SZ_3H   = (long)BR_ * 3072;

constexpr long OFF_IMG0  = 0;
constexpr long OFF_V1    = OFF_IMG0  + SZ_IMG0;
constexpr long OFF_V2    = OFF_V1    + SZ_V;
constexpr long OFF_RV    = OFF_V2    + SZ_V;
constexpr long OFF_QAQR  = OFF_RV    + SZ_RV;     // [BR,2048] = [qa|qrepr]
constexpr long OFF_VREPR1= OFF_QAQR  + SZ_2H;     // [2BR,1024] (VREPR1;VREPRV)
constexpr long OFF_OUT   = OFF_VREPR1+ 2*SZ_H;    // [2BR,1024] (OUT;OUTV)
constexpr long OFF_QKV3  = OFF_OUT   + 2*SZ_H;    // [BR,3072]
constexpr long OFF_NEIGH = OFF_QKV3  + SZ_3H;
constexpr long OFF_QAQR2 = OFF_NEIGH + SZ_H;
constexpr long OFF_VREPR2= OFF_QAQR2 + SZ_2H;
constexpr long OFF_OUT2  = OFF_VREPR2+ SZ_H;
constexpr long OFF_BIASAQN = OFF_OUT2 + SZ_H;     // 2048 floats
constexpr long SCRATCH_TOTAL = OFF_BIASAQN + 2048;

__device__ float g_scratch[SCRATCH_TOTAL];

// ---------------------------------------------------------------------------
// bf16 ACTIVATION planes (hi at off, lo at off+ATOTAL). Zero-initialized:
// pad columns never written -> stay zero -> no K guards in GEMM.
// NOTE: ABF_IMG0 and ABF_IMGF are contiguous -> V1+V2 GEMM fused (M=25088).
// ---------------------------------------------------------------------------
constexpr long ABF_IMG0  = 0;                          // [12544][512]
constexpr long ABF_IMGF  = ABF_IMG0  + 12544L * 512;   // [12544][512]
constexpr long ABF_RV    = ABF_IMGF  + 12544L * 512;   // [1536][640]
constexpr long ABF_QEMB  = ABF_RV    + 1536L * 640;    // [1536][1024]
constexpr long ABF_VEMB12= ABF_QEMB  + 1536L * 1024;   // [3072][512]
constexpr long ABF_VEMB3 = ABF_VEMB12+ 3072L * 512;    // [1536][512]
constexpr long ABF_OUT   = ABF_VEMB3 + 1536L * 512;    // [3072][1024]
constexpr long ABF_CTX   = ABF_OUT   + 3072L * 1024;   // [1536][1024]
constexpr long ABF_CAT   = ABF_CTX   + 1536L * 1024;   // [1536][1664]
constexpr long ABF_UQ    = ABF_CAT   + 1536L * 1664;   // [1536][1024]
constexpr long ABF_OUTF  = ABF_UQ    + 1536L * 1024;   // [1536][1024]
constexpr long ATOTAL    = ABF_OUTF  + 1536L * 1024;

__device__ __align__(256) __nv_bfloat16 g_abf[2 * ATOTAL];

// ---------------------------------------------------------------------------
// bf16 WEIGHT planes (transposed [Npad][Kpad], hi at off, lo at off+WTOTAL)
// ---------------------------------------------------------------------------
constexpr long WOFF_QC  = 0;                           // [1024][640]
constexpr long WOFF_AV  = WOFF_QC  + 1024L * 640;      // [1024][512]
constexpr long WOFF_AQN = WOFF_AV  + 1024L * 512;      // [2048][1024]
constexpr long WOFF_VN  = WOFF_AQN + 2048L * 1024;     // [1024][512]
constexpr long WOFF_QKV = WOFF_VN  + 1024L * 512;      // [3072][1024]
constexpr long WOFF_WO  = WOFF_QKV + 3072L * 1024;     // [1024][1024]
constexpr long WOFF_UQC = WOFF_WO  + 1024L * 1024;     // [1024][1664]
constexpr long WOFF_CLS = WOFF_UQC + 1024L * 1664;     // [2048][1024]
constexpr long WTOTAL   = WOFF_CLS + 2048L * 1024;

__device__ __align__(256) __nv_bfloat16 g_wbf[2 * WTOTAL];

// ---------------------------------------------------------------------------
// helpers
// ---------------------------------------------------------------------------
__device__ __forceinline__ uint32_t smem_u32(const void* p) {
    uint32_t a;
    asm("{ .reg .u64 t; cvta.to.shared.u64 t, %1; cvt.u32.u64 %0, t; }" : "=r"(a) : "l"(p));
    return a;
}
__device__ __forceinline__ void stsplit(long base, float v) {
    __nv_bfloat16 h = __float2bfloat16(v);
    g_abf[base] = h;
    g_abf[base + ATOTAL] = __float2bfloat16(v - __bfloat162float(h));
}
__device__ __forceinline__ void ldm_x4(uint32_t* r, uint32_t addr) {
    asm volatile("ldmatrix.sync.aligned.m8n8.x4.shared.b16 {%0,%1,%2,%3}, [%4];"
                 : "=r"(r[0]), "=r"(r[1]), "=r"(r[2]), "=r"(r[3]) : "r"(addr));
}
__device__ __forceinline__ void mma16816(float* c, const uint32_t* a, const uint32_t* b) {
    asm volatile(
        "mma.sync.aligned.m16n8k16.row.col.f32.bf16.bf16.f32 "
        "{%0,%1,%2,%3}, {%4,%5,%6,%7}, {%8,%9}, {%0,%1,%2,%3};"
        : "+f"(c[0]), "+f"(c[1]), "+f"(c[2]), "+f"(c[3])
        : "r"(a[0]), "r"(a[1]), "r"(a[2]), "r"(a[3]), "r"(b[0]), "r"(b[1]));
}
__device__ __forceinline__ void cpa16(uint32_t s, const void* g) {
    asm volatile("cp.async.cg.shared.global [%0], [%1], 16;" :: "r"(s), "l"(g));
}
#define CP_COMMIT() asm volatile("cp.async.commit_group;" ::: "memory")
#define CP_WAIT0()  asm volatile("cp.async.wait_group 0;" ::: "memory")

// ---------------------------------------------------------------------------
// megaconv: ALL weight transposes + bf16 splits in ONE launch
// ---------------------------------------------------------------------------
struct WAll {
    const float* W[11];
    int K[11], N[11], tilesK[11];
    int pre[12];
    long off[11];
};

__global__ void megaconv_kernel(WAll P)
{
    __shared__ float tile[32][33];
    int bx = blockIdx.x;
    int w = 0;
    while (bx >= P.pre[w + 1]) w++;
    int tix = bx - P.pre[w];
    int tK  = P.tilesK[w];
    int k0  = (tix % tK) * 32;
    int n0  = (tix / tK) * 32;
    int K = P.K[w], N = P.N[w], Kp = tK * 32;
    const float* W = P.W[w];
    long off = P.off[w];

    int tx = threadIdx.x, ty = threadIdx.y;
#pragma unroll
    for (int i = 0; i < 32; i += 8) {
        int k = k0 + ty + i, n = n0 + tx;
        tile[ty + i][tx] = (k < K && n < N) ? W[(size_t)k * N + n] : 0.f;
    }
    __syncthreads();
#pragma unroll
    for (int i = 0; i < 32; i += 8) {
        int n = n0 + ty + i, k = k0 + tx;
        float v = tile[tx][ty + i];
        __nv_bfloat16 h = __float2bfloat16(v);
        __nv_bfloat16 l = __float2bfloat16(v - __bfloat162float(h));
        long o = off + (long)n * Kp + k;
        g_wbf[o] = h;
        g_wbf[o + WTOTAL] = l;
    }
}

// img_feat fp32 -> bf16 split; plus pack [aq_b|qn_b] bias
__global__ void convf_kernel(const float* __restrict__ imgf,
                             const float* __restrict__ b0,
                             const float* __restrict__ b1)
{
    long idx = (long)blockIdx.x * 256 + threadIdx.x;
    if (idx < SZ_IMG0) {
        stsplit(ABF_IMGF + idx, imgf[idx]);
    } else {
        long i = idx - SZ_IMG0;
        if (i < 1024)      g_scratch[OFF_BIASAQN + i] = b0[i];
        else if (i < 2048) g_scratch[OFF_BIASAQN + i] = b1[i - 1024];
    }
}

// ---------------------------------------------------------------------------
// HMMA bf16-split GEMM, warp tile 64x64 (BM=128) / 32x64 (BM=64).
// 128 threads = 4 warps in 2x2. All operands pre-split bf16, cp.async
// mainloop, double-buffered padded smem (BKP=40 -> conflict-free LDSM).
// ---------------------------------------------------------------------------
template<int BM, int MAXCTA>
__global__ __launch_bounds__(128, MAXCTA)
void mma_gemm_kernel(long aOff, long wOff,
                     const float* __restrict__ biasPtr, long biasOff,
                     float* CExt, long offC, long offCbf,
                     int M, int N, int Kp, int act)
{
    constexpr int BN = 128, BKP = 40;
    constexpr int MI  = BM / 32;             // 16-row m-tiles per warp
    constexpr int NT  = 8;                   // n8-tiles per warp (warp N = 64)
    constexpr int ASZ = BM * BKP;            // bf16 elems
    constexpr int BSZ = BN * BKP;
    constexpr int STG = 2 * ASZ + 2 * BSZ;
    constexpr uint32_t ASZ2 = ASZ * 2, BSZ2 = BSZ * 2;

    extern __shared__ __align__(16) __nv_bfloat16 sm[];
    const __nv_bfloat16* Ahp = g_abf + aOff;
    const __nv_bfloat16* Alp = g_abf + aOff + ATOTAL;
    const __nv_bfloat16* Bwh = g_wbf + wOff;
    const __nv_bfloat16* Bwl = g_wbf + wOff + WTOTAL;
    const float* bias = biasPtr ? biasPtr
                      : (biasOff >= 0 ? (const float*)(g_scratch + biasOff) : nullptr);

    const int tid  = threadIdx.x;
    const int wid  = tid >> 5, lane = tid & 31;
    const int brow = blockIdx.y * BM, bcol = blockIdx.x * BN;
    const int wm   = (wid >> 1) * (BM / 2);   // warp row (0..1)
    const int wn   = (wid & 1) * 64;          // warp col (0..1)
    const uint32_t sb = smem_u32(sm);

    auto cpAll = [&](int t, int s) {
        const uint32_t st = sb + (uint32_t)(s * STG) * 2;
#pragma unroll
        for (int l = 0; l < BM / 32; l++) {
            int idx = tid + l * 128;
            int row = idx >> 2, seg = idx & 3;
            size_t go = (size_t)(brow + row) * Kp + t * 32 + seg * 8;
            uint32_t so = (uint32_t)(row * BKP + seg * 8) * 2;
            cpa16(st + so,        Ahp + go);
            cpa16(st + ASZ2 + so, Alp + go);
        }
#pragma unroll
        for (int l = 0; l < 4; l++) {
            int idx = tid + l * 128;
            int row = idx >> 2, seg = idx & 3;
            size_t go = (size_t)(bcol + row) * Kp + t * 32 + seg * 8;
            uint32_t so = (uint32_t)(row * BKP + seg * 8) * 2;
            cpa16(st + 2 * ASZ2 + so,        Bwh + go);
            cpa16(st + 2 * ASZ2 + BSZ2 + so, Bwl + go);
        }
    };

    float acc[MI][NT][4];
#pragma unroll
    for (int i = 0; i < MI; i++)
#pragma unroll
        for (int j = 0; j < NT; j++)
#pragma unroll
            for (int q = 0; q < 4; q++) acc[i][j][q] = 0.f;

    const int nCh = Kp / 32;

    cpAll(0, 0); CP_COMMIT();
    CP_WAIT0();
    __syncthreads();

    const int aRow = (lane & 7) + ((lane >> 3) & 1) * 8;
    const int aCol = (lane >> 4) * 8;
    const int bRow = (lane & 7) + ((lane >> 4) & 1) * 8;
    const int bCol = ((lane >> 3) & 1) * 8;

    for (int t = 0; t < nCh; t++) {
        const int s = t & 1;
        if (t + 1 < nCh) { cpAll(t + 1, s ^ 1); CP_COMMIT(); }

        const uint32_t ahB = sb + (uint32_t)(s * STG) * 2;
        const uint32_t alB = ahB + ASZ2;
        const uint32_t bhB = alB + ASZ2;
        const uint32_t blB = bhB + BSZ2;

#pragma unroll
        for (int ks = 0; ks < 2; ks++) {
            uint32_t ah[MI][4], al[MI][4];
#pragma unroll
            for (int mi = 0; mi < MI; mi++) {
                uint32_t off = (uint32_t)((wm + mi * 16 + aRow) * BKP + ks * 16 + aCol) * 2;
                ldm_x4(ah[mi], ahB + off);
                ldm_x4(al[mi], alB + off);
            }
            uint32_t bh[NT][2], bl[NT][2];
#pragma unroll
            for (int bt = 0; bt < NT / 2; bt++) {
                uint32_t off = (uint32_t)((wn + bt * 16 + bRow) * BKP + ks * 16 + bCol) * 2;
                uint32_t r[4];
                ldm_x4(r, bhB + off);
                bh[2 * bt][0] = r[0]; bh[2 * bt][1] = r[1];
                bh[2 * bt + 1][0] = r[2]; bh[2 * bt + 1][1] = r[3];
                ldm_x4(r, blB + off);
                bl[2 * bt][0] = r[0]; bl[2 * bt][1] = r[1];
                bl[2 * bt + 1][0] = r[2]; bl[2 * bt + 1][1] = r[3];
            }
#pragma unroll
            for (int mi = 0; mi < MI; mi++)
#pragma unroll
                for (int ni = 0; ni < NT; ni++) {
                    mma16816(acc[mi][ni], ah[mi], bh[ni]);
                    mma16816(acc[mi][ni], ah[mi], bl[ni]);
                    mma16816(acc[mi][ni], al[mi], bh[ni]);
                }
        }

        if (t + 1 < nCh) {
            CP_WAIT0();
            __syncthreads();
        }
    }

    // epilogue
    float* C = CExt ? CExt : (g_scratch + offC);
#pragma unroll
    for (int mi = 0; mi < MI; mi++) {
#pragma unroll
        for (int ni = 0; ni < NT; ni++) {
            int r0 = brow + wm + mi * 16 + (lane >> 2);
            int c0 = bcol + wn + ni * 8 + 2 * (lane & 3);
#pragma unroll
            for (int half = 0; half < 2; half++) {
                int gr = r0 + half * 8;
                float v0 = acc[mi][ni][2 * half + 0];
                float v1 = acc[mi][ni][2 * half + 1];
                if (offCbf >= 0) {
                    if (bias) { v0 += bias[c0]; v1 += bias[c0 + 1]; }
                    if (act)  { v0 = fmaxf(v0, 0.f); v1 = fmaxf(v1, 0.f); }
                    __nv_bfloat16 h0 = __float2bfloat16(v0);
                    __nv_bfloat16 h1 = __float2bfloat16(v1);
                    __nv_bfloat16 l0 = __float2bfloat16(v0 - __bfloat162float(h0));
                    __nv_bfloat16 l1 = __float2bfloat16(v1 - __bfloat162float(h1));
                    long o = offCbf + (long)gr * N + c0;
                    uint32_t hp = (uint32_t)__bfloat16_as_ushort(h0)
                                | ((uint32_t)__bfloat16_as_ushort(h1) << 16);
                    uint32_t lp = (uint32_t)__bfloat16_as_ushort(l0)
                                | ((uint32_t)__bfloat16_as_ushort(l1) << 16);
                    *(uint32_t*)&g_abf[o] = hp;
                    *(uint32_t*)&g_abf[o + ATOTAL] = lp;
                } else {
                    if (c0 < N) {
                        float o = v0 + (bias ? bias[c0] : 0.f);
                        if (act) o = fmaxf(o, 0.f);
                        C[(size_t)gr * N + c0] = o;
                    }
                    if (c0 + 1 < N) {
                        float o = v1 + (bias ? bias[c0 + 1] : 0.f);
                        if (act) o = fmaxf(o, 0.f);
                        C[(size_t)gr * N + c0 + 1] = o;
                    }
                }
            }
        }
    }
}

constexpr int SMEM_128 = 2 * (2 * 128 * 40 + 2 * 128 * 40) * 2;  // 81920 B
constexpr int SMEM_64  = 2 * (2 * 64 * 40 + 2 * 128 * 40) * 2;   // 61440 B

static inline void tgemm(long aOff, long wOff, const float* bias, long biasOff,
                         float* CExt, long offC, long offCbf,
                         int M, int N, int Np, int Kp, int act)
{
    if (M >= 4096) {
        dim3 grid(Np / 128, M / 128);
        mma_gemm_kernel<128, 2><<<grid, 128, SMEM_128>>>(aOff, wOff, bias, biasOff,
                                                         CExt, offC, offCbf, M, N, Kp, act);
    } else {
        dim3 grid(Np / 128, M / 64);
        mma_gemm_kernel<64, 3><<<grid, 128, SMEM_64>>>(aOff, wOff, bias, biasOff,
                                                       CExt, offC, offCbf, M, N, Kp, act);
    }
}

// ---------------------------------------------------------------------------
// img0[b,k,c] = v_org[b,c,k]  (fp32 for att6 + bf16 split for GEMM)
// ---------------------------------------------------------------------------
__global__ void transpose_kernel(const float* __restrict__ v_org)
{
    long idx = (long)blockIdx.x * 256 + threadIdx.x;
    if (idx >= SZ_IMG0) return;
    int  c = (int)(idx % C_);
    long t = idx / C_;
    int  k = (int)(t % K_);
    int  b = (int)(t / K_);
    float v = v_org[((long)b * C_ + c) * K_ + k];
    g_scratch[OFF_IMG0 + idx] = v;
    stsplit(ABF_IMG0 + idx, v);
}

// ---------------------------------------------------------------------------
// rv gather (fp32 for concat + bf16 split, row stride 640)
// ---------------------------------------------------------------------------
__global__ void gather_rv_kernel(const int* __restrict__ gt_verb,
                                 const int* __restrict__ role_idx,
                                 const float* __restrict__ vt,
                                 const float* __restrict__ rt)
{
    long idx = (long)blockIdx.x * 256 + threadIdx.x;
    if (idx >= SZ_RV) return;
    int e = (int)(idx % TWO_E);
    int n = (int)(idx / TWO_E);
    int b = n / R_;
    float val = (e < E_) ? vt[(long)gt_verb[b] * E_ + e]
                         : rt[(long)role_idx[n] * E_ + (e - E_)];
    g_scratch[OFF_RV + idx] = val;
    stsplit(ABF_RV + (long)n * 640 + e, val);
}

// ---------------------------------------------------------------------------
// Visual attention (block per batch element, 6 roles) -> bf16 split vemb
// ---------------------------------------------------------------------------
__global__ __launch_bounds__(256) void att6_kernel(
    long offV, long offQA, int qStride,
    const float* __restrict__ aoW, const float* __restrict__ aoB,
    const float* __restrict__ imgPtr, long offImg, long abfOut)
{
    int b  = blockIdx.x;
    int n0 = b * R_;
    const float* V   = g_scratch + offV + (long)b * K_ * H_;
    const float* img = imgPtr ? (imgPtr + (long)b * K_ * C_)
                              : (g_scratch + offImg + (long)b * K_ * C_);

    __shared__ float qa[R_][H_];
    __shared__ float attw[R_][K_ + 1];

    int tid = threadIdx.x, wid = tid >> 5, lane = tid & 31;

    for (int idx = tid; idx < R_ * H_; idx += 256) {
        int r = idx / H_, h = idx % H_;
        qa[r][h] = g_scratch[offQA + (long)(n0 + r) * qStride + h] * aoW[h];
    }
    __syncthreads();

    for (int k = wid; k < K_; k += 8) {
        const float* vk = V + (long)k * H_;
        float s0=0,s1=0,s2=0,s3=0,s4=0,s5=0;
        for (int h = lane; h < H_; h += 32) {
            float v = vk[h];
            s0 = fmaf(v, qa[0][h], s0); s1 = fmaf(v, qa[1][h], s1);
            s2 = fmaf(v, qa[2][h], s2); s3 = fmaf(v, qa[3][h], s3);
            s4 = fmaf(v, qa[4][h], s4); s5 = fmaf(v, qa[5][h], s5);
        }
#pragma unroll
        for (int o = 16; o; o >>= 1) {
            s0 += __shfl_xor_sync(0xffffffffu, s0, o);
            s1 += __shfl_xor_sync(0xffffffffu, s1, o);
            s2 += __shfl_xor_sync(0xffffffffu, s2, o);
            s3 += __shfl_xor_sync(0xffffffffu, s3, o);
            s4 += __shfl_xor_sync(0xffffffffu, s4, o);
            s5 += __shfl_xor_sync(0xffffffffu, s5, o);
        }
        if (lane == 0) {
            float ab = aoB[0];
            attw[0][k] = s0 + ab; attw[1][k] = s1 + ab; attw[2][k] = s2 + ab;
            attw[3][k] = s3 + ab; attw[4][k] = s4 + ab; attw[5][k] = s5 + ab;
        }
    }
    __syncthreads();

    if (tid < R_) {
        float mx = -1e30f;
        for (int k = 0; k < K_; k++) mx = fmaxf(mx, attw[tid][k]);
        float sum = 0.f;
        for (int k = 0; k < K_; k++) sum += expf(attw[tid][k] - mx);
        float inv = 1.f / sum;
        for (int k = 0; k < K_; k++) attw[tid][k] = expf(attw[tid][k] - mx) * inv;
    }
    __syncthreads();

    for (int c = tid; c < C_; c += 256) {
        float a0=0,a1=0,a2=0,a3=0,a4=0,a5=0;
#pragma unroll 7
        for (int k = 0; k < K_; k++) {
            float f = img[(long)k * C_ + c];
            a0 = fmaf(attw[0][k], f, a0); a1 = fmaf(attw[1][k], f, a1);
            a2 = fmaf(attw[2][k], f, a2); a3 = fmaf(attw[3][k], f, a3);
            a4 = fmaf(attw[4][k], f, a4); a5 = fmaf(attw[5][k], f, a5);
        }
        long base = abfOut + (long)n0 * C_ + c;
        stsplit(base,          a0); stsplit(base + C_,     a1);
        stsplit(base + 2 * C_, a2); stsplit(base + 3 * C_, a3);
        stsplit(base + 4 * C_, a4); stsplit(base + 5 * C_, a5);
    }
}

// ---------------------------------------------------------------------------
// MFB pool: fp32 out + optional bf16 split
// ---------------------------------------------------------------------------
__global__ void mfb_kernel(long offQ, int qStride, int qWrap,
                           long offV, long offOut, long abfOut)
{
    int n = blockIdx.x;
    const float* q = g_scratch + offQ   + (long)(n % qWrap) * qStride;
    const float* v = g_scratch + offV   + (long)n * H_;
    float*       o = g_scratch + offOut + (long)n * H_;
    int tid = threadIdx.x;

    float s = 0.f;
    for (int h = tid; h < H_; h += 256) {
        float z = q[h] * v[h];
        s += fabsf(z);
    }
    __shared__ float red[8];
#pragma unroll
    for (int off = 16; off; off >>= 1) s += __shfl_xor_sync(0xffffffffu, s, off);
    if ((tid & 31) == 0) red[tid >> 5] = s;
    __syncthreads();
    float tot = 0.f;
#pragma unroll
    for (int i = 0; i < 8; i++) tot += red[i];
    float inv = 1.f / fmaxf(sqrtf(tot), 1e-12f);

    for (int h = tid; h < H_; h += 256) {
        float z = q[h] * v[h];
        float sg = (z > 0.f) ? sqrtf(z) : -sqrtf(-z);
        float r = sg * inv;
        o[h] = r;
        if (abfOut >= 0) stsplit(abfOut + (long)n * H_ + h, r);
    }
}

// ---------------------------------------------------------------------------
// Masked role attention -> ctx as bf16 split
// ---------------------------------------------------------------------------
__global__ void role_att_kernel(const int* __restrict__ mask)
{
    int b = blockIdx.x;
    const float* base = g_scratch + OFF_QKV3 + (long)b * R_ * 3072;

    __shared__ float sc[R_][R_];
    __shared__ float attn[R_][R_];
    int tid = threadIdx.x, wid = tid >> 5, lane = tid & 31;

    for (int p = wid; p < R_ * R_; p += 8) {
        int i = p / R_, j = p % R_;
        const float* qh = base + (long)i * 3072;
        const float* kh = base + (long)j * 3072 + 1024;
        float s = 0.f;
        for (int h = lane; h < H_; h += 32)
            s = fmaf(qh[h], kh[h], s);
#pragma unroll
        for (int o = 16; o; o >>= 1) s += __shfl_xor_sync(0xffffffffu, s, o);
        if (lane == 0) {
            bool valid = (i != j) && (mask[((long)b * R_ + i) * R_ + j] > 0);
            sc[i][j] = valid ? s * (1.f / 32.f) : -1e9f;
        }
    }
    __syncthreads();

    if (tid < R_ * R_) {
        int i = tid / R_, j = tid % R_;
        float mx = -1e30f;
        for (int jj = 0; jj < R_; jj++) mx = fmaxf(mx, sc[i][jj]);
        float sum = 0.f;
        for (int jj = 0; jj < R_; jj++) sum += expf(sc[i][jj] - mx);
        attn[i][j] = expf(sc[i][j] - mx) / sum;
    }
    __syncthreads();

    for (int idx = tid; idx < R_ * H_; idx += 256) {
        int i = idx / H_, h = idx % H_;
        float acc = 0.f;
#pragma unroll
        for (int j = 0; j < R_; j++)
            acc = fmaf(attn[i][j], base[(long)j * 3072 + 2048 + h], acc);
        stsplit(ABF_CTX + (long)(b * R_ + i) * H_ + h, acc);
    }
}

// ---------------------------------------------------------------------------
// cat = [neigh | rv] -> bf16 split only (stride 1664)
// ---------------------------------------------------------------------------
__global__ void concat_kernel()
{
    long idx = (long)blockIdx.x * 256 + threadIdx.x;
    if (idx >= (long)BR_ * CATW) return;
    int col = (int)(idx % CATW);
    int n   = (int)(idx / CATW);
    float v = (col < H_) ? g_scratch[OFF_NEIGH + (long)n * H_ + col]
                         : g_scratch[OFF_RV + (long)n * TWO_E + (col - H_)];
    stsplit(ABF_CAT + (long)n * 1664 + col, v);
}

// ---------------------------------------------------------------------------
// gated fusion -> bf16 split only
// ---------------------------------------------------------------------------
__global__ void combine_kernel()
{
    long idx = (long)blockIdx.x * 256 + threadIdx.x;
    if (idx >= SZ_H) return;
    float o2 = g_scratch[OFF_OUT2 + idx];
    float ov = g_scratch[OFF_OUT + SZ_H + idx];
    float a0 = g_scratch[OFF_OUT + idx];
    float g  = 1.f / (1.f + expf(-(o2 + ov)));
    stsplit(ABF_OUTF + idx, (1.f - g) * ov + g * tanhf(o2 + a0));
}

// ---------------------------------------------------------------------------
// Launch sequence
// ---------------------------------------------------------------------------
extern "C" void kernel_launch(void* const* d_in, const int* in_sizes, int n_in,
                              void* d_out, int out_size)
{
    const float* v_org    = (const float*)d_in[0];
    const float* img_feat = (const float*)d_in[1];
    const int*   gt_verb  = (const int*)d_in[2];
    const int*   role_idx = (const int*)d_in[3];
    const int*   mask     = (const int*)d_in[4];
    const float* verb_t   = (const float*)d_in[5];
    const float* role_t   = (const float*)d_in[6];
    const float* qc_W = (const float*)d_in[7];   const float* qc_b = (const float*)d_in[8];
    const float* av_W = (const float*)d_in[9];   const float* av_b = (const float*)d_in[10];
    const float* aq_W = (const float*)d_in[11];  const float* aq_b = (const float*)d_in[12];
    const float* ao_W = (const float*)d_in[13];  const float* ao_b = (const float*)d_in[14];
    const float* vn_W = (const float*)d_in[15];  const float* vn_b = (const float*)d_in[16];
    const float* qn_W = (const float*)d_in[17];  const float* qn_b = (const float*)d_in[18];
    const float* Wq   = (const float*)d_in[19];
    const float* Wk   = (const float*)d_in[20];
    const float* Wv   = (const float*)d_in[21];
    const float* Wo   = (const float*)d_in[22];
    const float* uqc_W = (const float*)d_in[23]; const float* uqc_b = (const float*)d_in[24];
    const float* cls_W = (const float*)d_in[25]; const float* cls_b = (const float*)d_in[26];

    cudaFuncSetAttribute((const void*)mma_gemm_kernel<128, 2>,
                         cudaFuncAttributeMaxDynamicSharedMemorySize, SMEM_128);
    cudaFuncSetAttribute((const void*)mma_gemm_kernel<64, 3>,
                         cudaFuncAttributeMaxDynamicSharedMemorySize, SMEM_64);

    // megaconv descriptor table
    WAll P;
    const float* Ws[11] = {qc_W, av_W, aq_W, qn_W, vn_W, Wq, Wk, Wv, Wo, uqc_W, cls_W};
    int  Ks[11]  = {600, 512, 1024, 1024, 512, 1024, 1024, 1024, 1024, CATW, 1024};
    int  Ns[11]  = {1024,1024,1024, 1024, 1024,1024, 1024, 1024, 1024, 1024, NL_};
    int  tK[11]  = {20,  16,  32,   32,   16,  32,   32,   32,   32,   52,   32};
    int  Nps[11] = {1024,1024,1024, 1024, 1024,1024, 1024, 1024, 1024, 1024, 2048};
    long offs[11]= {WOFF_QC, WOFF_AV, WOFF_AQN, WOFF_AQN + 1024L * 1024, WOFF_VN,
                    WOFF_QKV, WOFF_QKV + 1024L * 1024, WOFF_QKV + 2048L * 1024,
                    WOFF_WO, WOFF_UQC, WOFF_CLS};
    int pre = 0;
    for (int i = 0; i < 11; i++) {
        P.W[i] = Ws[i]; P.K[i] = Ks[i]; P.N[i] = Ns[i];
        P.tilesK[i] = tK[i]; P.off[i] = offs[i];
        P.pre[i] = pre;
        pre += tK[i] * (Nps[i] / 32);
    }
    P.pre[11] = pre;

    // 0: transpose, 1: img_feat convert (+bias pack), 2: megaconv,
    // 3: FUSED V1+V2 GEMM (M=25088) — profiled slot
    transpose_kernel<<<(int)((SZ_IMG0 + 255) / 256), 256>>>(v_org);
    convf_kernel<<<(int)((SZ_IMG0 + 2048 + 255) / 256), 256>>>(img_feat, aq_b, qn_b);
    megaconv_kernel<<<pre, dim3(32, 8)>>>(P);
    tgemm(ABF_IMG0, WOFF_AV, av_b, -1, nullptr, OFF_V1, -1,
          2 * B_ * K_, 1024, 1024, 512, 1);
    gather_rv_kernel<<<(int)((SZ_RV + 255) / 256), 256>>>(gt_verb, role_idx, verb_t, role_t);

    // query chain (QEMB -> bf16 only)
    tgemm(ABF_RV, WOFF_QC, qc_b, -1, nullptr, 0, ABF_QEMB,
          BR_, 1024, 1024, 640, 1);
    tgemm(ABF_QEMB, WOFF_AQN, nullptr, OFF_BIASAQN, nullptr, OFF_QAQR, -1,
          BR_, 2048, 2048, 1024, 1);

    // attention 1 + attention-verb
    att6_kernel<<<B_, 256>>>(OFF_V1, OFF_QAQR, 2048, ao_W, ao_b, nullptr, OFF_IMG0, ABF_VEMB12);
    att6_kernel<<<B_, 256>>>(OFF_V2, OFF_QAQR, 2048, ao_W, ao_b, img_feat, 0,
                             ABF_VEMB12 + (long)BR_ * 512);

    // fused VN over [VEMB1;VEMB2]
    tgemm(ABF_VEMB12, WOFF_VN, vn_b, -1, nullptr, OFF_VREPR1, -1,
          2 * BR_, 1024, 1024, 512, 1);

    // fused MFB (OUT rows get bf16 split)
    mfb_kernel<<<2 * BR_, 256>>>(OFF_QAQR + 1024, 2048, BR_, OFF_VREPR1, OFF_OUT, ABF_OUT);

    // role-node neighbour attention
    tgemm(ABF_OUT, WOFF_QKV, nullptr, -1, nullptr, OFF_QKV3, -1,
          BR_, 3072, 3072, 1024, 0);
    role_att_kernel<<<B_, 256>>>(mask);
    tgemm(ABF_CTX, WOFF_WO, nullptr, -1, nullptr, OFF_NEIGH, -1,
          BR_, 1024, 1024, 1024, 0);

    // updated query
    concat_kernel<<<(int)(((long)BR_ * CATW + 255) / 256), 256>>>();
    tgemm(ABF_CAT, WOFF_UQC, uqc_b, -1, nullptr, 0, ABF_UQ,
          BR_, 1024, 1024, 1664, 1);
    tgemm(ABF_UQ, WOFF_AQN, nullptr, OFF_BIASAQN, nullptr, OFF_QAQR2, -1,
          BR_, 2048, 2048, 1024, 1);

    // attention 2
    att6_kernel<<<B_, 256>>>(OFF_V1, OFF_QAQR2, 2048, ao_W, ao_b, nullptr, OFF_IMG0, ABF_VEMB3);
    tgemm(ABF_VEMB3, WOFF_VN, vn_b, -1, nullptr, OFF_VREPR2, -1,
          BR_, 1024, 1024, 512, 1);
    mfb_kernel<<<BR_, 256>>>(OFF_QAQR2 + 1024, 2048, BR_, OFF_VREPR2, OFF_OUT2, -1);

    // gated fusion
    combine_kernel<<<(int)((SZ_H + 255) / 256), 256>>>();

    // classifier -> d_out
    tgemm(ABF_OUTF, WOFF_CLS, cls_b, -1, (float*)d_out, 0, -1,
          BR_, NL_, 2048, 1024, 0);
}